// round 5
// baseline (speedup 1.0000x reference)
#include <cuda_runtime.h>
#include <cuda_fp16.h>
#include <cstdint>

#define NPTS  8192
#define KNB   16
#define DIN   259
#define KPAD  320
#define NOUT  512
#define NEDGE (NPTS * KNB)

// ------------------------- device scratch (no allocs) ----------------------
__device__ __align__(16) float4 g_xyzw[NPTS];
__device__ int    g_nbr[NEDGE];
__device__ __align__(16) __half g_Xh[NPTS * KPAD];
__device__ __align__(16) __half g_W1h[2][KPAD * NOUT];
__device__ __align__(16) __half g_W2h[2][256 * 256];
__device__ __align__(16) float  g_A[NPTS * 256];
__device__ __align__(16) float  g_B[NPTS * 256];
__device__ __align__(16) float  g_H[NPTS * 256];
__device__ __align__(16) __half g_H1[NEDGE * 256];

// ------------------------- mma helpers -------------------------------------
__device__ __forceinline__ uint32_t sptr(const void* p) {
    return (uint32_t)__cvta_generic_to_shared(p);
}
__device__ __forceinline__ void ldsm4(uint32_t* r, uint32_t a) {
    asm volatile("ldmatrix.sync.aligned.m8n8.x4.shared.b16 {%0,%1,%2,%3},[%4];\n"
                 : "=r"(r[0]), "=r"(r[1]), "=r"(r[2]), "=r"(r[3]) : "r"(a));
}
__device__ __forceinline__ void ldsm4t(uint32_t* r, uint32_t a) {
    asm volatile("ldmatrix.sync.aligned.m8n8.x4.trans.shared.b16 {%0,%1,%2,%3},[%4];\n"
                 : "=r"(r[0]), "=r"(r[1]), "=r"(r[2]), "=r"(r[3]) : "r"(a));
}
__device__ __forceinline__ void mma16816(float* c, const uint32_t* a, uint32_t b0, uint32_t b1) {
    asm volatile(
        "mma.sync.aligned.m16n8k16.row.col.f32.f16.f16.f32 "
        "{%0,%1,%2,%3},{%4,%5,%6,%7},{%8,%9},{%0,%1,%2,%3};\n"
        : "+f"(c[0]), "+f"(c[1]), "+f"(c[2]), "+f"(c[3])
        : "r"(a[0]), "r"(a[1]), "r"(a[2]), "r"(a[3]), "r"(b0), "r"(b1));
}

// Shared 128x64 output tile GEMM mainloop (BK=64, 8 warps, warp grid 4x2,
// each warp 32x32). acc[mt][nt][4]: mt = 16-row halves, nt = 8-col tiles.
__device__ __forceinline__ void gemm_tile(const __half* __restrict__ Ag, int lda,
                                          const __half* __restrict__ Bg, int ldb,
                                          int m0, int n0, int Ksz, float acc[2][4][4]) {
    __shared__ __align__(16) __half sA[128 * 72];
    __shared__ __align__(16) __half sB[64 * 72];
    int tid = threadIdx.x, lane = tid & 31, warp = tid >> 5;
    int wm = warp & 3, wn = warp >> 2;
#pragma unroll
    for (int a = 0; a < 2; ++a)
#pragma unroll
        for (int b = 0; b < 4; ++b)
#pragma unroll
            for (int c = 0; c < 4; ++c) acc[a][b][c] = 0.f;

    for (int k0 = 0; k0 < Ksz; k0 += 64) {
        __syncthreads();
#pragma unroll
        for (int i = tid; i < 1024; i += 256) {
            int r = i >> 3, c = (i & 7) * 8;
            *(uint4*)&sA[r * 72 + c] = *(const uint4*)&Ag[(size_t)(m0 + r) * lda + k0 + c];
        }
#pragma unroll
        for (int i = tid; i < 512; i += 256) {
            int r = i >> 3, c = (i & 7) * 8;
            *(uint4*)&sB[r * 72 + c] = *(const uint4*)&Bg[(size_t)(k0 + r) * ldb + n0 + c];
        }
        __syncthreads();
#pragma unroll
        for (int kk = 0; kk < 4; ++kk) {
            uint32_t af[2][4];
#pragma unroll
            for (int mt = 0; mt < 2; ++mt)
                ldsm4(af[mt], sptr(&sA[(wm * 32 + mt * 16 + (lane & 15)) * 72 + kk * 16 + ((lane >> 4) * 8)]));
#pragma unroll
            for (int t = 0; t < 2; ++t) {
                uint32_t bf[4];
                ldsm4t(bf, sptr(&sB[(kk * 16 + (lane & 15)) * 72 + wn * 32 + t * 16 + ((lane >> 4) * 8)]));
#pragma unroll
                for (int mt = 0; mt < 2; ++mt) {
                    mma16816(acc[mt][2 * t + 0], af[mt], bf[0], bf[1]);
                    mma16816(acc[mt][2 * t + 1], af[mt], bf[2], bf[3]);
                }
            }
        }
    }
}

// ------------------------- prep kernels ------------------------------------
__global__ void k_prep_xyzw(const float* __restrict__ xyz) {
    int i = blockIdx.x * blockDim.x + threadIdx.x;
    if (i < NPTS) {
        float x = xyz[3 * i], y = xyz[3 * i + 1], z = xyz[3 * i + 2];
        g_xyzw[i] = make_float4(x, y, z, x * x + y * y + z * z);
    }
}

__global__ void k_prep_w1(const float* __restrict__ W1a, const float* __restrict__ W1b) {
    int idx = blockIdx.x * blockDim.x + threadIdx.x;
    if (idx >= 2 * KPAD * NOUT) return;
    int layer = idx / (KPAD * NOUT);
    int rem = idx % (KPAD * NOUT);
    int k = rem / NOUT, n = rem % NOUT;
    const float* W1 = layer ? W1b : W1a;
    float v = 0.f;
    if (k < DIN) {
        if (n < 256) v = W1[k * 256 + n] - W1[(DIN + k) * 256 + n];
        else         v = W1[(DIN + k) * 256 + (n - 256)];
    }
    g_W1h[layer][rem] = __float2half_rn(v);
}

__global__ void k_prep_w2(const float* __restrict__ W2a, const float* __restrict__ W2b) {
    int idx = blockIdx.x * blockDim.x + threadIdx.x;
    if (idx >= 2 * 256 * 256) return;
    int layer = idx >> 16, rem = idx & 65535;
    g_W2h[layer][rem] = __float2half_rn((layer ? W2b : W2a)[rem]);
}

// Xh[r][c] = src (c<256) | xyz (256..258) | 0 pad
__global__ void k_build_x(const float* __restrict__ feat, const float* __restrict__ xyz, int useH) {
    int idx = blockIdx.x * blockDim.x + threadIdx.x;
    if (idx >= NPTS * KPAD) return;
    int r = idx / KPAD, c = idx % KPAD;
    const float* s = useH ? g_H : feat;
    float v = 0.f;
    if (c < 256)      v = s[r * 256 + c];
    else if (c < DIN) v = xyz[r * 3 + (c - 256)];
    g_Xh[idx] = __float2half_rn(v);
}

// ------------------------- KNN ---------------------------------------------
__global__ __launch_bounds__(256) void k_knn() {
    __shared__ float4 tile[2048];
    int lane = threadIdx.x & 31, warp = threadIdx.x >> 5;
    int row = blockIdx.x * 8 + warp;
    float4 me = g_xyzw[row];

    float bd[16]; int bi[16];
#pragma unroll
    for (int p = 0; p < 16; ++p) { bd[p] = 3.4e38f; bi[p] = 0x7fffffff; }

    for (int t = 0; t < 4; ++t) {
        __syncthreads();
        for (int i = threadIdx.x; i < 2048; i += 256) tile[i] = g_xyzw[t * 2048 + i];
        __syncthreads();
        int jg0 = t * 2048;
        for (int jj = lane; jj < 2048; jj += 32) {
            float4 o = tile[jj];
            float key = fmaf(-2.f * me.x, o.x, o.w);
            key = fmaf(-2.f * me.y, o.y, key);
            key = fmaf(-2.f * me.z, o.z, key);
            int jg = jg0 + jj;
            if (jg != row && key < bd[15]) {
                bd[15] = key; bi[15] = jg;
#pragma unroll
                for (int p = 15; p > 0; --p) {
                    if (bd[p] < bd[p - 1]) {
                        float td = bd[p]; bd[p] = bd[p - 1]; bd[p - 1] = td;
                        int ti = bi[p]; bi[p] = bi[p - 1]; bi[p - 1] = ti;
                    }
                }
            }
        }
    }
    // merge 32 sorted per-lane lists -> global top-16 (min key, index tiebreak)
    float v = bd[0]; int vi = bi[0];
    int keep = 0;
    for (int r = 0; r < 16; ++r) {
        float mv = v; int mi = vi;
#pragma unroll
        for (int off = 16; off > 0; off >>= 1) {
            float ov = __shfl_xor_sync(0xffffffffu, mv, off);
            int   oi = __shfl_xor_sync(0xffffffffu, mi, off);
            if (ov < mv || (ov == mv && oi < mi)) { mv = ov; mi = oi; }
        }
        if (lane == r) keep = mi;
        if (v == mv && vi == mi) {
#pragma unroll
            for (int p = 0; p < 15; ++p) { bd[p] = bd[p + 1]; bi[p] = bi[p + 1]; }
            bd[15] = 3.4e38f; bi[15] = 0x7fffffff;
            v = bd[0]; vi = bi[0];
        }
    }
    if (lane < 16) g_nbr[row * 16 + lane] = keep;
}

// ------------------------- dense GEMM1 (X @ W1cat) -------------------------
__global__ __launch_bounds__(256) void k_gemm1(int layer, const float* __restrict__ b1) {
    float acc[2][4][4];
    int m0 = blockIdx.x * 128, n0 = blockIdx.y * 64;
    gemm_tile(g_Xh, KPAD, g_W1h[layer], NOUT, m0, n0, KPAD, acc);

    int lane = threadIdx.x & 31, warp = threadIdx.x >> 5;
    int wm = warp & 3, wn = warp >> 2;
    int gid = lane >> 2, c2 = (lane & 3) * 2;
#pragma unroll
    for (int mt = 0; mt < 2; ++mt)
#pragma unroll
        for (int nt = 0; nt < 4; ++nt) {
            int row = m0 + wm * 32 + mt * 16 + gid;
            int col = n0 + wn * 32 + nt * 8 + c2;
            float* a4 = acc[mt][nt];
            if (col < 256) {
                float bb0 = b1[col], bb1 = b1[col + 1];
                *(float2*)&g_A[row * 256 + col]       = make_float2(a4[0] + bb0, a4[1] + bb1);
                *(float2*)&g_A[(row + 8) * 256 + col] = make_float2(a4[2] + bb0, a4[3] + bb1);
            } else {
                int cb = col - 256;
                *(float2*)&g_B[row * 256 + cb]       = make_float2(a4[0], a4[1]);
                *(float2*)&g_B[(row + 8) * 256 + cb] = make_float2(a4[2], a4[3]);
            }
        }
}

// ------------------------- H1 = relu(A_i + B_j) ----------------------------
__global__ __launch_bounds__(256) void k_h1build() {
    int e = blockIdx.x * blockDim.x + threadIdx.x;   // over NEDGE*64 float4s
    if (e >= NEDGE * 64) return;
    int r = e >> 6, c4 = e & 63;
    int p = r >> 4;
    int j = g_nbr[r];
    float4 a = *(const float4*)&g_A[p * 256 + c4 * 4];
    float4 b = *(const float4*)&g_B[j * 256 + c4 * 4];
    __half2 h0 = __floats2half2_rn(fmaxf(a.x + b.x, 0.f), fmaxf(a.y + b.y, 0.f));
    __half2 h1 = __floats2half2_rn(fmaxf(a.z + b.z, 0.f), fmaxf(a.w + b.w, 0.f));
    uint2 pk;
    pk.x = *(uint32_t*)&h0; pk.y = *(uint32_t*)&h1;
    *(uint2*)&g_H1[r * 256 + c4 * 4] = pk;
}

// ------------------------- GEMM2: H1 @ W2, fused 16-row max + b2 -----------
// toOut: 0 -> write layer result to g_H (device symbol resolved ON DEVICE),
//        1 -> write to harness output pointer.
__global__ __launch_bounds__(256) void k_gemm2(int layer, const float* __restrict__ b2,
                                               float* __restrict__ outArg, int toOut) {
    float acc[2][4][4];
    int m0 = blockIdx.x * 128, n0 = blockIdx.y * 64;
    gemm_tile(g_H1, 256, g_W2h[layer], 256, m0, n0, 256, acc);

    float* out = toOut ? outArg : g_H;   // device-side symbol resolution
    int lane = threadIdx.x & 31, warp = threadIdx.x >> 5;
    int wm = warp & 3, wn = warp >> 2;
#pragma unroll
    for (int mt = 0; mt < 2; ++mt) {
        int p = (m0 + wm * 32 + mt * 16) >> 4;       // 16 rows = one point
#pragma unroll
        for (int nt = 0; nt < 4; ++nt) {
            float m0v = fmaxf(acc[mt][nt][0], acc[mt][nt][2]);
            float m1v = fmaxf(acc[mt][nt][1], acc[mt][nt][3]);
#pragma unroll
            for (int off = 4; off < 32; off <<= 1) {
                m0v = fmaxf(m0v, __shfl_xor_sync(0xffffffffu, m0v, off));
                m1v = fmaxf(m1v, __shfl_xor_sync(0xffffffffu, m1v, off));
            }
            if (lane < 4) {
                int col = n0 + wn * 32 + nt * 8 + lane * 2;
                out[p * 256 + col]     = m0v + b2[col];
                out[p * 256 + col + 1] = m1v + b2[col + 1];
            }
        }
    }
}

// ------------------------- launch ------------------------------------------
extern "C" void kernel_launch(void* const* d_in, const int* in_sizes, int n_in,
                              void* d_out, int out_size) {
    const float* xyz  = (const float*)d_in[0];
    const float* feat = (const float*)d_in[1];
    const float* W1a  = (const float*)d_in[2];
    const float* b1a  = (const float*)d_in[3];
    const float* W2a  = (const float*)d_in[4];
    const float* b2a  = (const float*)d_in[5];
    const float* W1b  = (const float*)d_in[6];
    const float* b1b  = (const float*)d_in[7];
    const float* W2b  = (const float*)d_in[8];
    const float* b2b  = (const float*)d_in[9];
    float* out = (float*)d_out;

    k_prep_xyzw<<<32, 256>>>(xyz);
    k_knn<<<1024, 256>>>();
    k_prep_w1<<<(2 * KPAD * NOUT + 255) / 256, 256>>>(W1a, W1b);
    k_prep_w2<<<512, 256>>>(W2a, W2b);

    dim3 g1(NPTS / 128, NOUT / 64);
    dim3 g2(NEDGE / 128, 256 / 64);

    // layer a
    k_build_x<<<(NPTS * KPAD + 255) / 256, 256>>>(feat, xyz, 0);
    k_gemm1<<<g1, 256>>>(0, b1a);
    k_h1build<<<(NEDGE * 64 + 255) / 256, 256>>>();
    k_gemm2<<<g2, 256>>>(0, b2a, nullptr, 0);

    // layer b
    k_build_x<<<(NPTS * KPAD + 255) / 256, 256>>>(nullptr, xyz, 1);
    k_gemm1<<<g1, 256>>>(1, b1b);
    k_h1build<<<(NEDGE * 64 + 255) / 256, 256>>>();
    k_gemm2<<<g2, 256>>>(1, b2b, out, 1);
}

// round 7
// speedup vs baseline: 1.1038x; 1.1038x over previous
#include <cuda_runtime.h>
#include <cuda_fp16.h>
#include <cstdint>

#define NPTS  8192
#define KNB   16
#define DIN   259
#define KPAD  320
#define NOUT  512
#define NEDGE (NPTS * KNB)

// dynamic smem: double-buffered tiles. sA[2][128*72] + sB[2][64*72] halves
#define SA_STRIDE (128 * 72)
#define SB_STRIDE (64 * 72)
#define SMEM_BYTES ((2 * SA_STRIDE + 2 * SB_STRIDE) * 2)

// ------------------------- device scratch (no allocs) ----------------------
__device__ __align__(16) float4 g_xyzw[NPTS];
__device__ int    g_nbr[NEDGE];
__device__ __align__(16) __half g_Xh[NPTS * KPAD];
__device__ __align__(16) __half g_W1h[2][KPAD * NOUT];
__device__ __align__(16) __half g_W2h[2][256 * 256];
__device__ __align__(16) float  g_A[NPTS * 256];
__device__ __align__(16) float  g_B[NPTS * 256];
__device__ __align__(16) float  g_H[NPTS * 256];
__device__ __align__(16) __half g_H1[NEDGE * 256];

// ------------------------- asm helpers -------------------------------------
__device__ __forceinline__ uint32_t sptr(const void* p) {
    return (uint32_t)__cvta_generic_to_shared(p);
}
__device__ __forceinline__ void ldsm4(uint32_t* r, uint32_t a) {
    asm volatile("ldmatrix.sync.aligned.m8n8.x4.shared.b16 {%0,%1,%2,%3},[%4];\n"
                 : "=r"(r[0]), "=r"(r[1]), "=r"(r[2]), "=r"(r[3]) : "r"(a));
}
__device__ __forceinline__ void ldsm4t(uint32_t* r, uint32_t a) {
    asm volatile("ldmatrix.sync.aligned.m8n8.x4.trans.shared.b16 {%0,%1,%2,%3},[%4];\n"
                 : "=r"(r[0]), "=r"(r[1]), "=r"(r[2]), "=r"(r[3]) : "r"(a));
}
__device__ __forceinline__ void mma16816(float* c, const uint32_t* a, uint32_t b0, uint32_t b1) {
    asm volatile(
        "mma.sync.aligned.m16n8k16.row.col.f32.f16.f16.f32 "
        "{%0,%1,%2,%3},{%4,%5,%6,%7},{%8,%9},{%0,%1,%2,%3};\n"
        : "+f"(c[0]), "+f"(c[1]), "+f"(c[2]), "+f"(c[3])
        : "r"(a[0]), "r"(a[1]), "r"(a[2]), "r"(a[3]), "r"(b0), "r"(b1));
}
__device__ __forceinline__ void cp16(void* dst, const void* src) {
    asm volatile("cp.async.cg.shared.global [%0],[%1],16;\n"
                 :: "r"(sptr(dst)), "l"(src));
}
#define CP_COMMIT() asm volatile("cp.async.commit_group;\n")
#define CP_WAIT0()  asm volatile("cp.async.wait_group 0;\n")

// ------------------------- pipelined GEMM mainloop -------------------------
// 128x64 output tile, BK=64, 8 warps (4x2), warp tile 32x32.
// 2-stage cp.async double buffer: prefetch k+1 while computing k.
__device__ __forceinline__ void gemm_tile(const __half* __restrict__ Ag, int lda,
                                          const __half* __restrict__ Bg, int ldb,
                                          int m0, int n0, int Ksz, float acc[2][4][4]) {
    extern __shared__ __align__(16) __half dyn[];
    __half* sA = dyn;                    // [2][SA_STRIDE]
    __half* sB = dyn + 2 * SA_STRIDE;    // [2][SB_STRIDE]
    int tid = threadIdx.x, lane = tid & 31, warp = tid >> 5;
    int wm = warp & 3, wn = warp >> 2;
#pragma unroll
    for (int a = 0; a < 2; ++a)
#pragma unroll
        for (int b = 0; b < 4; ++b)
#pragma unroll
            for (int c = 0; c < 4; ++c) acc[a][b][c] = 0.f;

    int nk = Ksz >> 6;

    // prefetch stage 0
    {
#pragma unroll
        for (int i = tid; i < 1024; i += 256) {
            int r = i >> 3, c = (i & 7) * 8;
            cp16(&sA[r * 72 + c], &Ag[(size_t)(m0 + r) * lda + c]);
        }
#pragma unroll
        for (int i = tid; i < 512; i += 256) {
            int r = i >> 3, c = (i & 7) * 8;
            cp16(&sB[r * 72 + c], &Bg[(size_t)r * ldb + n0 + c]);
        }
        CP_COMMIT();
    }

    int buf = 0;
    for (int kt = 0; kt < nk; ++kt) {
        CP_WAIT0();
        __syncthreads();
        if (kt + 1 < nk) {
            int k0 = (kt + 1) << 6;
            int nb = buf ^ 1;
#pragma unroll
            for (int i = tid; i < 1024; i += 256) {
                int r = i >> 3, c = (i & 7) * 8;
                cp16(&sA[nb * SA_STRIDE + r * 72 + c], &Ag[(size_t)(m0 + r) * lda + k0 + c]);
            }
#pragma unroll
            for (int i = tid; i < 512; i += 256) {
                int r = i >> 3, c = (i & 7) * 8;
                cp16(&sB[nb * SB_STRIDE + r * 72 + c], &Bg[(size_t)(k0 + r) * ldb + n0 + c]);
            }
            CP_COMMIT();
        }
        const __half* cA = sA + buf * SA_STRIDE;
        const __half* cB = sB + buf * SB_STRIDE;
#pragma unroll
        for (int kk = 0; kk < 4; ++kk) {
            uint32_t af[2][4];
#pragma unroll
            for (int mt = 0; mt < 2; ++mt)
                ldsm4(af[mt], sptr(&cA[(wm * 32 + mt * 16 + (lane & 15)) * 72 + kk * 16 + ((lane >> 4) * 8)]));
#pragma unroll
            for (int t = 0; t < 2; ++t) {
                uint32_t bf[4];
                ldsm4t(bf, sptr(&cB[(kk * 16 + (lane & 15)) * 72 + wn * 32 + t * 16 + ((lane >> 4) * 8)]));
#pragma unroll
                for (int mt = 0; mt < 2; ++mt) {
                    mma16816(acc[mt][2 * t + 0], af[mt], bf[0], bf[1]);
                    mma16816(acc[mt][2 * t + 1], af[mt], bf[2], bf[3]);
                }
            }
        }
        buf ^= 1;
    }
}

// ------------------------- prep kernels ------------------------------------
__global__ void k_prep_xyzw(const float* __restrict__ xyz) {
    int i = blockIdx.x * blockDim.x + threadIdx.x;
    if (i < NPTS) {
        float x = xyz[3 * i], y = xyz[3 * i + 1], z = xyz[3 * i + 2];
        g_xyzw[i] = make_float4(x, y, z, x * x + y * y + z * z);
    }
}

__global__ void k_prep_w1(const float* __restrict__ W1a, const float* __restrict__ W1b) {
    int idx = blockIdx.x * blockDim.x + threadIdx.x;
    if (idx >= 2 * KPAD * NOUT) return;
    int layer = idx / (KPAD * NOUT);
    int rem = idx % (KPAD * NOUT);
    int k = rem / NOUT, n = rem % NOUT;
    const float* W1 = layer ? W1b : W1a;
    float v = 0.f;
    if (k < DIN) {
        if (n < 256) v = W1[k * 256 + n] - W1[(DIN + k) * 256 + n];
        else         v = W1[(DIN + k) * 256 + (n - 256)];
    }
    g_W1h[layer][rem] = __float2half_rn(v);
}

__global__ void k_prep_w2(const float* __restrict__ W2a, const float* __restrict__ W2b) {
    int idx = blockIdx.x * blockDim.x + threadIdx.x;
    if (idx >= 2 * 256 * 256) return;
    int layer = idx >> 16, rem = idx & 65535;
    g_W2h[layer][rem] = __float2half_rn((layer ? W2b : W2a)[rem]);
}

__global__ void k_build_x(const float* __restrict__ feat, const float* __restrict__ xyz, int useH) {
    int idx = blockIdx.x * blockDim.x + threadIdx.x;
    if (idx >= NPTS * KPAD) return;
    int r = idx / KPAD, c = idx % KPAD;
    const float* s = useH ? g_H : feat;
    float v = 0.f;
    if (c < 256)      v = s[r * 256 + c];
    else if (c < DIN) v = xyz[r * 3 + (c - 256)];
    g_Xh[idx] = __float2half_rn(v);
}

// ------------------------- KNN ---------------------------------------------
__global__ __launch_bounds__(256) void k_knn() {
    __shared__ float4 tile[2048];
    int lane = threadIdx.x & 31, warp = threadIdx.x >> 5;
    int row = blockIdx.x * 8 + warp;
    float4 me = g_xyzw[row];

    float bd[16]; int bi[16];
#pragma unroll
    for (int p = 0; p < 16; ++p) { bd[p] = 3.4e38f; bi[p] = 0x7fffffff; }

    for (int t = 0; t < 4; ++t) {
        __syncthreads();
        for (int i = threadIdx.x; i < 2048; i += 256) tile[i] = g_xyzw[t * 2048 + i];
        __syncthreads();
        int jg0 = t * 2048;
        for (int jj = lane; jj < 2048; jj += 32) {
            float4 o = tile[jj];
            float key = fmaf(-2.f * me.x, o.x, o.w);
            key = fmaf(-2.f * me.y, o.y, key);
            key = fmaf(-2.f * me.z, o.z, key);
            int jg = jg0 + jj;
            if (jg != row && key < bd[15]) {
                bd[15] = key; bi[15] = jg;
#pragma unroll
                for (int p = 15; p > 0; --p) {
                    if (bd[p] < bd[p - 1]) {
                        float td = bd[p]; bd[p] = bd[p - 1]; bd[p - 1] = td;
                        int ti = bi[p]; bi[p] = bi[p - 1]; bi[p - 1] = ti;
                    }
                }
            }
        }
    }
    float v = bd[0]; int vi = bi[0];
    int keep = 0;
    for (int r = 0; r < 16; ++r) {
        float mv = v; int mi = vi;
#pragma unroll
        for (int off = 16; off > 0; off >>= 1) {
            float ov = __shfl_xor_sync(0xffffffffu, mv, off);
            int   oi = __shfl_xor_sync(0xffffffffu, mi, off);
            if (ov < mv || (ov == mv && oi < mi)) { mv = ov; mi = oi; }
        }
        if (lane == r) keep = mi;
        if (v == mv && vi == mi) {
#pragma unroll
            for (int p = 0; p < 15; ++p) { bd[p] = bd[p + 1]; bi[p] = bi[p + 1]; }
            bd[15] = 3.4e38f; bi[15] = 0x7fffffff;
            v = bd[0]; vi = bi[0];
        }
    }
    if (lane < 16) g_nbr[row * 16 + lane] = keep;
}

// ------------------------- dense GEMM1 (X @ W1cat) -------------------------
__global__ __launch_bounds__(256) void k_gemm1(int layer, const float* __restrict__ b1) {
    float acc[2][4][4];
    int m0 = blockIdx.x * 128, n0 = blockIdx.y * 64;
    gemm_tile(g_Xh, KPAD, g_W1h[layer], NOUT, m0, n0, KPAD, acc);

    int lane = threadIdx.x & 31, warp = threadIdx.x >> 5;
    int wm = warp & 3, wn = warp >> 2;
    int gid = lane >> 2, c2 = (lane & 3) * 2;
#pragma unroll
    for (int mt = 0; mt < 2; ++mt)
#pragma unroll
        for (int nt = 0; nt < 4; ++nt) {
            int row = m0 + wm * 32 + mt * 16 + gid;
            int col = n0 + wn * 32 + nt * 8 + c2;
            float* a4 = acc[mt][nt];
            if (col < 256) {
                float bb0 = b1[col], bb1 = b1[col + 1];
                *(float2*)&g_A[row * 256 + col]       = make_float2(a4[0] + bb0, a4[1] + bb1);
                *(float2*)&g_A[(row + 8) * 256 + col] = make_float2(a4[2] + bb0, a4[3] + bb1);
            } else {
                int cb = col - 256;
                *(float2*)&g_B[row * 256 + cb]       = make_float2(a4[0], a4[1]);
                *(float2*)&g_B[(row + 8) * 256 + cb] = make_float2(a4[2], a4[3]);
            }
        }
}

// ------------------------- H1 = relu(A_i + B_j) ----------------------------
__global__ __launch_bounds__(256) void k_h1build() {
    int e = blockIdx.x * blockDim.x + threadIdx.x;
    if (e >= NEDGE * 64) return;
    int r = e >> 6, c4 = e & 63;
    int p = r >> 4;
    int j = g_nbr[r];
    float4 a = *(const float4*)&g_A[p * 256 + c4 * 4];
    float4 b = *(const float4*)&g_B[j * 256 + c4 * 4];
    __half2 h0 = __floats2half2_rn(fmaxf(a.x + b.x, 0.f), fmaxf(a.y + b.y, 0.f));
    __half2 h1 = __floats2half2_rn(fmaxf(a.z + b.z, 0.f), fmaxf(a.w + b.w, 0.f));
    uint2 pk;
    pk.x = *(uint32_t*)&h0; pk.y = *(uint32_t*)&h1;
    *(uint2*)&g_H1[r * 256 + c4 * 4] = pk;
}

// ------------------------- GEMM2: H1 @ W2, fused 16-row max + b2 -----------
__global__ __launch_bounds__(256) void k_gemm2(int layer, const float* __restrict__ b2,
                                               float* __restrict__ outArg, int toOut) {
    float acc[2][4][4];
    int m0 = blockIdx.x * 128, n0 = blockIdx.y * 64;
    gemm_tile(g_H1, 256, g_W2h[layer], 256, m0, n0, 256, acc);

    float* out = toOut ? outArg : g_H;   // device-side symbol resolution
    int lane = threadIdx.x & 31, warp = threadIdx.x >> 5;
    int wm = warp & 3, wn = warp >> 2;
#pragma unroll
    for (int mt = 0; mt < 2; ++mt) {
        int p = (m0 + wm * 32 + mt * 16) >> 4;
#pragma unroll
        for (int nt = 0; nt < 4; ++nt) {
            float m0v = fmaxf(acc[mt][nt][0], acc[mt][nt][2]);
            float m1v = fmaxf(acc[mt][nt][1], acc[mt][nt][3]);
#pragma unroll
            for (int off = 4; off < 32; off <<= 1) {
                m0v = fmaxf(m0v, __shfl_xor_sync(0xffffffffu, m0v, off));
                m1v = fmaxf(m1v, __shfl_xor_sync(0xffffffffu, m1v, off));
            }
            if (lane < 4) {
                int col = n0 + wn * 32 + nt * 8 + lane * 2;
                out[p * 256 + col]     = m0v + b2[col];
                out[p * 256 + col + 1] = m1v + b2[col + 1];
            }
        }
    }
}

// ------------------------- launch ------------------------------------------
extern "C" void kernel_launch(void* const* d_in, const int* in_sizes, int n_in,
                              void* d_out, int out_size) {
    const float* xyz  = (const float*)d_in[0];
    const float* feat = (const float*)d_in[1];
    const float* W1a  = (const float*)d_in[2];
    const float* b1a  = (const float*)d_in[3];
    const float* W2a  = (const float*)d_in[4];
    const float* b2a  = (const float*)d_in[5];
    const float* W1b  = (const float*)d_in[6];
    const float* b1b  = (const float*)d_in[7];
    const float* W2b  = (const float*)d_in[8];
    const float* b2b  = (const float*)d_in[9];
    float* out = (float*)d_out;

    cudaFuncSetAttribute(k_gemm1, cudaFuncAttributeMaxDynamicSharedMemorySize, SMEM_BYTES);
    cudaFuncSetAttribute(k_gemm2, cudaFuncAttributeMaxDynamicSharedMemorySize, SMEM_BYTES);

    k_prep_xyzw<<<32, 256>>>(xyz);
    k_knn<<<1024, 256>>>();
    k_prep_w1<<<(2 * KPAD * NOUT + 255) / 256, 256>>>(W1a, W1b);
    k_prep_w2<<<512, 256>>>(W2a, W2b);

    dim3 g1(NPTS / 128, NOUT / 64);
    dim3 g2(NEDGE / 128, 256 / 64);

    // layer a
    k_build_x<<<(NPTS * KPAD + 255) / 256, 256>>>(feat, xyz, 0);
    k_gemm1<<<g1, 256, SMEM_BYTES>>>(0, b1a);
    k_h1build<<<(NEDGE * 64 + 255) / 256, 256>>>();
    k_gemm2<<<g2, 256, SMEM_BYTES>>>(0, b2a, nullptr, 0);

    // layer b
    k_build_x<<<(NPTS * KPAD + 255) / 256, 256>>>(nullptr, xyz, 1);
    k_gemm1<<<g1, 256, SMEM_BYTES>>>(1, b1b);
    k_h1build<<<(NEDGE * 64 + 255) / 256, 256>>>();
    k_gemm2<<<g2, 256, SMEM_BYTES>>>(1, b2b, out, 1);
}

// round 8
// speedup vs baseline: 1.1166x; 1.0116x over previous
#include <cuda_runtime.h>
#include <cuda_fp16.h>
#include <cstdint>

#define NPTS  8192
#define KNB   16
#define DIN   259
#define KPAD  320
#define NOUT  512
#define NEDGE (NPTS * KNB)

// 128x128 block tile, BK=64, double-buffered dynamic smem
#define SA_STRIDE (128 * 72)     // A: 128 rows x 64 k (pad 72)
#define SB_STRIDE (64 * 136)     // B: 64 k rows x 128 n (pad 136)
#define SMEM_BYTES ((2 * SA_STRIDE + 2 * SB_STRIDE) * 2)

// ------------------------- device scratch (no allocs) ----------------------
__device__ __align__(16) float4 g_xyzw[NPTS];
__device__ int    g_nbr[NEDGE];
__device__ __align__(16) __half g_Xh[NPTS * KPAD];
__device__ __align__(16) __half g_W1h[2][KPAD * NOUT];
__device__ __align__(16) __half g_W2h[2][256 * 256];
__device__ __align__(16) float  g_A[NPTS * 256];
__device__ __align__(16) float  g_B[NPTS * 256];
__device__ __align__(16) float  g_H[NPTS * 256];
__device__ __align__(16) __half g_H1[NEDGE * 256];

// ------------------------- asm helpers -------------------------------------
__device__ __forceinline__ uint32_t sptr(const void* p) {
    return (uint32_t)__cvta_generic_to_shared(p);
}
__device__ __forceinline__ void ldsm4(uint32_t* r, uint32_t a) {
    asm volatile("ldmatrix.sync.aligned.m8n8.x4.shared.b16 {%0,%1,%2,%3},[%4];\n"
                 : "=r"(r[0]), "=r"(r[1]), "=r"(r[2]), "=r"(r[3]) : "r"(a));
}
__device__ __forceinline__ void ldsm4t(uint32_t* r, uint32_t a) {
    asm volatile("ldmatrix.sync.aligned.m8n8.x4.trans.shared.b16 {%0,%1,%2,%3},[%4];\n"
                 : "=r"(r[0]), "=r"(r[1]), "=r"(r[2]), "=r"(r[3]) : "r"(a));
}
__device__ __forceinline__ void mma16816(float* c, const uint32_t* a, uint32_t b0, uint32_t b1) {
    asm volatile(
        "mma.sync.aligned.m16n8k16.row.col.f32.f16.f16.f32 "
        "{%0,%1,%2,%3},{%4,%5,%6,%7},{%8,%9},{%0,%1,%2,%3};\n"
        : "+f"(c[0]), "+f"(c[1]), "+f"(c[2]), "+f"(c[3])
        : "r"(a[0]), "r"(a[1]), "r"(a[2]), "r"(a[3]), "r"(b0), "r"(b1));
}
__device__ __forceinline__ void cp16(void* dst, const void* src) {
    asm volatile("cp.async.cg.shared.global [%0],[%1],16;\n"
                 :: "r"(sptr(dst)), "l"(src));
}
#define CP_COMMIT() asm volatile("cp.async.commit_group;\n")
#define CP_WAIT0()  asm volatile("cp.async.wait_group 0;\n")

// ------------------------- pipelined GEMM mainloop -------------------------
// 128x128 output tile, BK=64, 8 warps (wm 0..1 x wn 0..3), warp tile 64x32.
// acc[mt 0..3][nt 0..3][4]
__device__ __forceinline__ void gemm_tile(const __half* __restrict__ Ag, int lda,
                                          const __half* __restrict__ Bg, int ldb,
                                          int m0, int n0, int Ksz, float acc[4][4][4]) {
    extern __shared__ __align__(16) __half dyn[];
    __half* sA = dyn;                    // [2][SA_STRIDE]
    __half* sB = dyn + 2 * SA_STRIDE;    // [2][SB_STRIDE]
    int tid = threadIdx.x, lane = tid & 31, warp = tid >> 5;
    int wm = warp & 1, wn = warp >> 1;
#pragma unroll
    for (int a = 0; a < 4; ++a)
#pragma unroll
        for (int b = 0; b < 4; ++b)
#pragma unroll
            for (int c = 0; c < 4; ++c) acc[a][b][c] = 0.f;

    int nk = Ksz >> 6;

    // prefetch stage 0
#pragma unroll
    for (int i = tid; i < 1024; i += 256) {
        int r = i >> 3, c = (i & 7) * 8;
        cp16(&sA[r * 72 + c], &Ag[(size_t)(m0 + r) * lda + c]);
    }
#pragma unroll
    for (int i = tid; i < 1024; i += 256) {
        int r = i >> 4, c = (i & 15) * 8;
        cp16(&sB[r * 136 + c], &Bg[(size_t)r * ldb + n0 + c]);
    }
    CP_COMMIT();

    int buf = 0;
    for (int kt = 0; kt < nk; ++kt) {
        CP_WAIT0();
        __syncthreads();
        if (kt + 1 < nk) {
            int k0 = (kt + 1) << 6;
            int nb = buf ^ 1;
#pragma unroll
            for (int i = tid; i < 1024; i += 256) {
                int r = i >> 3, c = (i & 7) * 8;
                cp16(&sA[nb * SA_STRIDE + r * 72 + c], &Ag[(size_t)(m0 + r) * lda + k0 + c]);
            }
#pragma unroll
            for (int i = tid; i < 1024; i += 256) {
                int r = i >> 4, c = (i & 15) * 8;
                cp16(&sB[nb * SB_STRIDE + r * 136 + c], &Bg[(size_t)(k0 + r) * ldb + n0 + c]);
            }
            CP_COMMIT();
        }
        const __half* cA = sA + buf * SA_STRIDE;
        const __half* cB = sB + buf * SB_STRIDE;
#pragma unroll
        for (int kk = 0; kk < 4; ++kk) {
            uint32_t af[4][4];
#pragma unroll
            for (int mt = 0; mt < 4; ++mt)
                ldsm4(af[mt], sptr(&cA[(wm * 64 + mt * 16 + (lane & 15)) * 72 + kk * 16 + ((lane >> 4) * 8)]));
#pragma unroll
            for (int t = 0; t < 2; ++t) {
                uint32_t bf[4];
                ldsm4t(bf, sptr(&cB[(kk * 16 + (lane & 15)) * 136 + wn * 32 + t * 16 + ((lane >> 4) * 8)]));
#pragma unroll
                for (int mt = 0; mt < 4; ++mt) {
                    mma16816(acc[mt][2 * t + 0], af[mt], bf[0], bf[1]);
                    mma16816(acc[mt][2 * t + 1], af[mt], bf[2], bf[3]);
                }
            }
        }
        buf ^= 1;
    }
}

// ------------------------- prep kernels ------------------------------------
__global__ void k_prep_xyzw(const float* __restrict__ xyz) {
    int i = blockIdx.x * blockDim.x + threadIdx.x;
    if (i < NPTS) {
        float x = xyz[3 * i], y = xyz[3 * i + 1], z = xyz[3 * i + 2];
        g_xyzw[i] = make_float4(x, y, z, x * x + y * y + z * z);
    }
}

__global__ void k_prep_w1(const float* __restrict__ W1a, const float* __restrict__ W1b) {
    int idx = blockIdx.x * blockDim.x + threadIdx.x;
    if (idx >= 2 * KPAD * NOUT) return;
    int layer = idx / (KPAD * NOUT);
    int rem = idx % (KPAD * NOUT);
    int k = rem / NOUT, n = rem % NOUT;
    const float* W1 = layer ? W1b : W1a;
    float v = 0.f;
    if (k < DIN) {
        if (n < 256) v = W1[k * 256 + n] - W1[(DIN + k) * 256 + n];
        else         v = W1[(DIN + k) * 256 + (n - 256)];
    }
    g_W1h[layer][rem] = __float2half_rn(v);
}

__global__ void k_prep_w2(const float* __restrict__ W2a, const float* __restrict__ W2b) {
    int idx = blockIdx.x * blockDim.x + threadIdx.x;
    if (idx >= 2 * 256 * 256) return;
    int layer = idx >> 16, rem = idx & 65535;
    g_W2h[layer][rem] = __float2half_rn((layer ? W2b : W2a)[rem]);
}

__global__ void k_build_x(const float* __restrict__ feat, const float* __restrict__ xyz, int useH) {
    int idx = blockIdx.x * blockDim.x + threadIdx.x;
    if (idx >= NPTS * KPAD) return;
    int r = idx / KPAD, c = idx % KPAD;
    const float* s = useH ? g_H : feat;
    float v = 0.f;
    if (c < 256)      v = s[r * 256 + c];
    else if (c < DIN) v = xyz[r * 3 + (c - 256)];
    g_Xh[idx] = __float2half_rn(v);
}

// ------------------------- KNN ---------------------------------------------
__global__ __launch_bounds__(256) void k_knn() {
    __shared__ float4 tile[2048];
    int lane = threadIdx.x & 31, warp = threadIdx.x >> 5;
    int row = blockIdx.x * 8 + warp;
    float4 me = g_xyzw[row];

    float bd[16]; int bi[16];
#pragma unroll
    for (int p = 0; p < 16; ++p) { bd[p] = 3.4e38f; bi[p] = 0x7fffffff; }

    for (int t = 0; t < 4; ++t) {
        __syncthreads();
        for (int i = threadIdx.x; i < 2048; i += 256) tile[i] = g_xyzw[t * 2048 + i];
        __syncthreads();
        int jg0 = t * 2048;
        for (int jj = lane; jj < 2048; jj += 32) {
            float4 o = tile[jj];
            float key = fmaf(-2.f * me.x, o.x, o.w);
            key = fmaf(-2.f * me.y, o.y, key);
            key = fmaf(-2.f * me.z, o.z, key);
            int jg = jg0 + jj;
            if (jg != row && key < bd[15]) {
                bd[15] = key; bi[15] = jg;
#pragma unroll
                for (int p = 15; p > 0; --p) {
                    if (bd[p] < bd[p - 1]) {
                        float td = bd[p]; bd[p] = bd[p - 1]; bd[p - 1] = td;
                        int ti = bi[p]; bi[p] = bi[p - 1]; bi[p - 1] = ti;
                    }
                }
            }
        }
    }
    float v = bd[0]; int vi = bi[0];
    int keep = 0;
    for (int r = 0; r < 16; ++r) {
        float mv = v; int mi = vi;
#pragma unroll
        for (int off = 16; off > 0; off >>= 1) {
            float ov = __shfl_xor_sync(0xffffffffu, mv, off);
            int   oi = __shfl_xor_sync(0xffffffffu, mi, off);
            if (ov < mv || (ov == mv && oi < mi)) { mv = ov; mi = oi; }
        }
        if (lane == r) keep = mi;
        if (v == mv && vi == mi) {
#pragma unroll
            for (int p = 0; p < 15; ++p) { bd[p] = bd[p + 1]; bi[p] = bi[p + 1]; }
            bd[15] = 3.4e38f; bi[15] = 0x7fffffff;
            v = bd[0]; vi = bi[0];
        }
    }
    if (lane < 16) g_nbr[row * 16 + lane] = keep;
}

// ------------------------- dense GEMM1 (X @ W1cat) -------------------------
__global__ __launch_bounds__(256) void k_gemm1(int layer, const float* __restrict__ b1) {
    float acc[4][4][4];
    int m0 = blockIdx.x * 128, n0 = blockIdx.y * 128;
    gemm_tile(g_Xh, KPAD, g_W1h[layer], NOUT, m0, n0, KPAD, acc);

    int lane = threadIdx.x & 31, warp = threadIdx.x >> 5;
    int wm = warp & 1, wn = warp >> 1;
    int gid = lane >> 2, c2 = (lane & 3) * 2;
#pragma unroll
    for (int mt = 0; mt < 4; ++mt)
#pragma unroll
        for (int nt = 0; nt < 4; ++nt) {
            int row = m0 + wm * 64 + mt * 16 + gid;
            int col = n0 + wn * 32 + nt * 8 + c2;
            float* a4 = acc[mt][nt];
            if (col < 256) {
                float bb0 = b1[col], bb1 = b1[col + 1];
                *(float2*)&g_A[row * 256 + col]       = make_float2(a4[0] + bb0, a4[1] + bb1);
                *(float2*)&g_A[(row + 8) * 256 + col] = make_float2(a4[2] + bb0, a4[3] + bb1);
            } else {
                int cb = col - 256;
                *(float2*)&g_B[row * 256 + cb]       = make_float2(a4[0], a4[1]);
                *(float2*)&g_B[(row + 8) * 256 + cb] = make_float2(a4[2], a4[3]);
            }
        }
}

// ------------------------- H1 = relu(A_i + B_j) ----------------------------
__global__ __launch_bounds__(256) void k_h1build() {
    int e = blockIdx.x * blockDim.x + threadIdx.x;
    if (e >= NEDGE * 64) return;
    int r = e >> 6, c4 = e & 63;
    int p = r >> 4;
    int j = g_nbr[r];
    float4 a = *(const float4*)&g_A[p * 256 + c4 * 4];
    float4 b = *(const float4*)&g_B[j * 256 + c4 * 4];
    __half2 h0 = __floats2half2_rn(fmaxf(a.x + b.x, 0.f), fmaxf(a.y + b.y, 0.f));
    __half2 h1 = __floats2half2_rn(fmaxf(a.z + b.z, 0.f), fmaxf(a.w + b.w, 0.f));
    uint2 pk;
    pk.x = *(uint32_t*)&h0; pk.y = *(uint32_t*)&h1;
    *(uint2*)&g_H1[r * 256 + c4 * 4] = pk;
}

// ------------------------- GEMM2: H1 @ W2, fused 16-row max + b2 -----------
__global__ __launch_bounds__(256) void k_gemm2(int layer, const float* __restrict__ b2,
                                               float* __restrict__ outArg, int toOut) {
    float acc[4][4][4];
    int m0 = blockIdx.x * 128, n0 = blockIdx.y * 128;
    gemm_tile(g_H1, 256, g_W2h[layer], 256, m0, n0, 256, acc);

    float* out = toOut ? outArg : g_H;   // device-side symbol resolution
    int lane = threadIdx.x & 31, warp = threadIdx.x >> 5;
    int wm = warp & 1, wn = warp >> 1;
#pragma unroll
    for (int mt = 0; mt < 4; ++mt) {
        int p = (m0 + wm * 64 + mt * 16) >> 4;
#pragma unroll
        for (int nt = 0; nt < 4; ++nt) {
            float m0v = fmaxf(acc[mt][nt][0], acc[mt][nt][2]);
            float m1v = fmaxf(acc[mt][nt][1], acc[mt][nt][3]);
#pragma unroll
            for (int off = 4; off < 32; off <<= 1) {
                m0v = fmaxf(m0v, __shfl_xor_sync(0xffffffffu, m0v, off));
                m1v = fmaxf(m1v, __shfl_xor_sync(0xffffffffu, m1v, off));
            }
            if (lane < 4) {
                int col = n0 + wn * 32 + nt * 8 + lane * 2;
                out[p * 256 + col]     = m0v + b2[col];
                out[p * 256 + col + 1] = m1v + b2[col + 1];
            }
        }
    }
}

// ------------------------- launch ------------------------------------------
extern "C" void kernel_launch(void* const* d_in, const int* in_sizes, int n_in,
                              void* d_out, int out_size) {
    const float* xyz  = (const float*)d_in[0];
    const float* feat = (const float*)d_in[1];
    const float* W1a  = (const float*)d_in[2];
    const float* b1a  = (const float*)d_in[3];
    const float* W2a  = (const float*)d_in[4];
    const float* b2a  = (const float*)d_in[5];
    const float* W1b  = (const float*)d_in[6];
    const float* b1b  = (const float*)d_in[7];
    const float* W2b  = (const float*)d_in[8];
    const float* b2b  = (const float*)d_in[9];
    float* out = (float*)d_out;

    cudaFuncSetAttribute(k_gemm1, cudaFuncAttributeMaxDynamicSharedMemorySize, SMEM_BYTES);
    cudaFuncSetAttribute(k_gemm2, cudaFuncAttributeMaxDynamicSharedMemorySize, SMEM_BYTES);

    k_prep_xyzw<<<32, 256>>>(xyz);
    k_knn<<<1024, 256>>>();
    k_prep_w1<<<(2 * KPAD * NOUT + 255) / 256, 256>>>(W1a, W1b);
    k_prep_w2<<<512, 256>>>(W2a, W2b);

    dim3 g1(NPTS / 128, NOUT / 128);   // 64 x 4
    dim3 g2(NEDGE / 128, 256 / 128);   // 1024 x 2

    // layer a
    k_build_x<<<(NPTS * KPAD + 255) / 256, 256>>>(feat, xyz, 0);
    k_gemm1<<<g1, 256, SMEM_BYTES>>>(0, b1a);
    k_h1build<<<(NEDGE * 64 + 255) / 256, 256>>>();
    k_gemm2<<<g2, 256, SMEM_BYTES>>>(0, b2a, nullptr, 0);

    // layer b
    k_build_x<<<(NPTS * KPAD + 255) / 256, 256>>>(nullptr, xyz, 1);
    k_gemm1<<<g1, 256, SMEM_BYTES>>>(1, b1b);
    k_h1build<<<(NEDGE * 64 + 255) / 256, 256>>>();
    k_gemm2<<<g2, 256, SMEM_BYTES>>>(1, b2b, out, 1);
}

// round 11
// speedup vs baseline: 1.1619x; 1.0405x over previous
#include <cuda_runtime.h>
#include <cuda_fp16.h>
#include <cstdint>

#define NPTS  8192
#define KNB   16
#define DIN   259
#define KPAD  320
#define NOUT  512
#define NEDGE (NPTS * KNB)

// ---- gemm1 smem (double-buffered A and B) ----
#define SA_STRIDE (128 * 72)
#define SB_STRIDE (64 * 136)
#define SMEM1_BYTES ((2 * SA_STRIDE + 2 * SB_STRIDE) * 2)

// ---- fused gemm2 smem: full-K A tile + double-buffered W2 ----
#define G2_A_STRIDE 264                       // halves per row (256 + 8 pad)
#define G2_A_HALVES (128 * G2_A_STRIDE)       // 33792
#define G2_W_STRIDE (64 * 136)                // one W2 stage
#define SMEM2_BYTES ((G2_A_HALVES + 2 * G2_W_STRIDE) * 2)   // 102400 B

// ------------------------- device scratch (no allocs) ----------------------
__device__ __align__(16) float4 g_xyzw[NPTS];
__device__ int    g_nbr[NEDGE];
__device__ __align__(16) __half g_Xh[NPTS * KPAD];
__device__ __align__(16) __half g_W1h[2][KPAD * NOUT];
__device__ __align__(16) __half g_W2h[2][256 * 256];
__device__ __align__(16) __half g_Ah[NPTS * 256];   // fp16, bias folded
__device__ __align__(16) __half g_Bh[NPTS * 256];   // fp16
__device__ __align__(16) float  g_H[NPTS * 256];

// ------------------------- asm helpers -------------------------------------
__device__ __forceinline__ uint32_t sptr(const void* p) {
    return (uint32_t)__cvta_generic_to_shared(p);
}
__device__ __forceinline__ void ldsm4(uint32_t* r, uint32_t a) {
    asm volatile("ldmatrix.sync.aligned.m8n8.x4.shared.b16 {%0,%1,%2,%3},[%4];\n"
                 : "=r"(r[0]), "=r"(r[1]), "=r"(r[2]), "=r"(r[3]) : "r"(a));
}
__device__ __forceinline__ void ldsm4t(uint32_t* r, uint32_t a) {
    asm volatile("ldmatrix.sync.aligned.m8n8.x4.trans.shared.b16 {%0,%1,%2,%3},[%4];\n"
                 : "=r"(r[0]), "=r"(r[1]), "=r"(r[2]), "=r"(r[3]) : "r"(a));
}
__device__ __forceinline__ void mma16816(float* c, const uint32_t* a, uint32_t b0, uint32_t b1) {
    asm volatile(
        "mma.sync.aligned.m16n8k16.row.col.f32.f16.f16.f32 "
        "{%0,%1,%2,%3},{%4,%5,%6,%7},{%8,%9},{%0,%1,%2,%3};\n"
        : "+f"(c[0]), "+f"(c[1]), "+f"(c[2]), "+f"(c[3])
        : "r"(a[0]), "r"(a[1]), "r"(a[2]), "r"(a[3]), "r"(b0), "r"(b1));
}
__device__ __forceinline__ void cp16(void* dst, const void* src) {
    asm volatile("cp.async.cg.shared.global [%0],[%1],16;\n"
                 :: "r"(sptr(dst)), "l"(src));
}
#define CP_COMMIT() asm volatile("cp.async.commit_group;\n")
#define CP_WAIT0()  asm volatile("cp.async.wait_group 0;\n")

// ------------------------- gemm1 pipelined mainloop ------------------------
// 128x128 tile, BK=64, 8 warps (wm 0..1 x wn 0..3), warp tile 64x32.
__device__ __forceinline__ void gemm_tile(const __half* __restrict__ Ag, int lda,
                                          const __half* __restrict__ Bg, int ldb,
                                          int m0, int n0, int Ksz, float acc[4][4][4]) {
    extern __shared__ __align__(16) __half dyn[];
    __half* sA = dyn;
    __half* sB = dyn + 2 * SA_STRIDE;
    int tid = threadIdx.x, lane = tid & 31, warp = tid >> 5;
    int wm = warp & 1, wn = warp >> 1;
#pragma unroll
    for (int a = 0; a < 4; ++a)
#pragma unroll
        for (int b = 0; b < 4; ++b)
#pragma unroll
            for (int c = 0; c < 4; ++c) acc[a][b][c] = 0.f;

    int nk = Ksz >> 6;
#pragma unroll
    for (int i = tid; i < 1024; i += 256) {
        int r = i >> 3, c = (i & 7) * 8;
        cp16(&sA[r * 72 + c], &Ag[(size_t)(m0 + r) * lda + c]);
    }
#pragma unroll
    for (int i = tid; i < 1024; i += 256) {
        int r = i >> 4, c = (i & 15) * 8;
        cp16(&sB[r * 136 + c], &Bg[(size_t)r * ldb + n0 + c]);
    }
    CP_COMMIT();

    int buf = 0;
    for (int kt = 0; kt < nk; ++kt) {
        CP_WAIT0();
        __syncthreads();
        if (kt + 1 < nk) {
            int k0 = (kt + 1) << 6;
            int nb = buf ^ 1;
#pragma unroll
            for (int i = tid; i < 1024; i += 256) {
                int r = i >> 3, c = (i & 7) * 8;
                cp16(&sA[nb * SA_STRIDE + r * 72 + c], &Ag[(size_t)(m0 + r) * lda + k0 + c]);
            }
#pragma unroll
            for (int i = tid; i < 1024; i += 256) {
                int r = i >> 4, c = (i & 15) * 8;
                cp16(&sB[nb * SB_STRIDE + r * 136 + c], &Bg[(size_t)(k0 + r) * ldb + n0 + c]);
            }
            CP_COMMIT();
        }
        const __half* cA = sA + buf * SA_STRIDE;
        const __half* cB = sB + buf * SB_STRIDE;
#pragma unroll
        for (int kk = 0; kk < 4; ++kk) {
            uint32_t af[4][4];
#pragma unroll
            for (int mt = 0; mt < 4; ++mt)
                ldsm4(af[mt], sptr(&cA[(wm * 64 + mt * 16 + (lane & 15)) * 72 + kk * 16 + ((lane >> 4) * 8)]));
#pragma unroll
            for (int t = 0; t < 2; ++t) {
                uint32_t bf[4];
                ldsm4t(bf, sptr(&cB[(kk * 16 + (lane & 15)) * 136 + wn * 32 + t * 16 + ((lane >> 4) * 8)]));
#pragma unroll
                for (int mt = 0; mt < 4; ++mt) {
                    mma16816(acc[mt][2 * t + 0], af[mt], bf[0], bf[1]);
                    mma16816(acc[mt][2 * t + 1], af[mt], bf[2], bf[3]);
                }
            }
        }
        buf ^= 1;
    }
}

// ------------------------- prep kernels ------------------------------------
__global__ void k_prep_xyzw(const float* __restrict__ xyz) {
    int i = blockIdx.x * blockDim.x + threadIdx.x;
    if (i < NPTS) {
        float x = xyz[3 * i], y = xyz[3 * i + 1], z = xyz[3 * i + 2];
        g_xyzw[i] = make_float4(x, y, z, x * x + y * y + z * z);
    }
}

__global__ void k_prep_w1(const float* __restrict__ W1a, const float* __restrict__ W1b) {
    int idx = blockIdx.x * blockDim.x + threadIdx.x;
    if (idx >= 2 * KPAD * NOUT) return;
    int layer = idx / (KPAD * NOUT);
    int rem = idx % (KPAD * NOUT);
    int k = rem / NOUT, n = rem % NOUT;
    const float* W1 = layer ? W1b : W1a;
    float v = 0.f;
    if (k < DIN) {
        if (n < 256) v = W1[k * 256 + n] - W1[(DIN + k) * 256 + n];
        else         v = W1[(DIN + k) * 256 + (n - 256)];
    }
    g_W1h[layer][rem] = __float2half_rn(v);
}

__global__ void k_prep_w2(const float* __restrict__ W2a, const float* __restrict__ W2b) {
    int idx = blockIdx.x * blockDim.x + threadIdx.x;
    if (idx >= 2 * 256 * 256) return;
    int layer = idx >> 16, rem = idx & 65535;
    g_W2h[layer][rem] = __float2half_rn((layer ? W2b : W2a)[rem]);
}

__global__ void k_build_x(const float* __restrict__ feat, const float* __restrict__ xyz, int useH) {
    int idx = blockIdx.x * blockDim.x + threadIdx.x;
    if (idx >= NPTS * KPAD) return;
    int r = idx / KPAD, c = idx % KPAD;
    const float* s = useH ? g_H : feat;
    float v = 0.f;
    if (c < 256)      v = s[r * 256 + c];
    else if (c < DIN) v = xyz[r * 3 + (c - 256)];
    g_Xh[idx] = __float2half_rn(v);
}

// ------------------------- KNN ---------------------------------------------
__global__ __launch_bounds__(256) void k_knn() {
    __shared__ float4 tile[2048];
    int lane = threadIdx.x & 31, warp = threadIdx.x >> 5;
    int row = blockIdx.x * 8 + warp;
    float4 me = g_xyzw[row];

    float bd[16]; int bi[16];
#pragma unroll
    for (int p = 0; p < 16; ++p) { bd[p] = 3.4e38f; bi[p] = 0x7fffffff; }

    for (int t = 0; t < 4; ++t) {
        __syncthreads();
        for (int i = threadIdx.x; i < 2048; i += 256) tile[i] = g_xyzw[t * 2048 + i];
        __syncthreads();
        int jg0 = t * 2048;
        for (int jj = lane; jj < 2048; jj += 32) {
            float4 o = tile[jj];
            float key = fmaf(-2.f * me.x, o.x, o.w);
            key = fmaf(-2.f * me.y, o.y, key);
            key = fmaf(-2.f * me.z, o.z, key);
            int jg = jg0 + jj;
            if (jg != row && key < bd[15]) {
                bd[15] = key; bi[15] = jg;
#pragma unroll
                for (int p = 15; p > 0; --p) {
                    if (bd[p] < bd[p - 1]) {
                        float td = bd[p]; bd[p] = bd[p - 1]; bd[p - 1] = td;
                        int ti = bi[p]; bi[p] = bi[p - 1]; bi[p - 1] = ti;
                    }
                }
            }
        }
    }
    float v = bd[0]; int vi = bi[0];
    int keep = 0;
    for (int r = 0; r < 16; ++r) {
        float mv = v; int mi = vi;
#pragma unroll
        for (int off = 16; off > 0; off >>= 1) {
            float ov = __shfl_xor_sync(0xffffffffu, mv, off);
            int   oi = __shfl_xor_sync(0xffffffffu, mi, off);
            if (ov < mv || (ov == mv && oi < mi)) { mv = ov; mi = oi; }
        }
        if (lane == r) keep = mi;
        if (v == mv && vi == mi) {
#pragma unroll
            for (int p = 0; p < 15; ++p) { bd[p] = bd[p + 1]; bi[p] = bi[p + 1]; }
            bd[15] = 3.4e38f; bi[15] = 0x7fffffff;
            v = bd[0]; vi = bi[0];
        }
    }
    if (lane < 16) g_nbr[row * 16 + lane] = keep;
}

// ------------------------- GEMM1: X @ W1cat -> fp16 A (bias) / B -----------
__global__ __launch_bounds__(256) void k_gemm1(int layer, const float* __restrict__ b1) {
    float acc[4][4][4];
    int m0 = blockIdx.x * 128, n0 = blockIdx.y * 128;
    gemm_tile(g_Xh, KPAD, g_W1h[layer], NOUT, m0, n0, KPAD, acc);

    int lane = threadIdx.x & 31, warp = threadIdx.x >> 5;
    int wm = warp & 1, wn = warp >> 1;
    int gid = lane >> 2, c2 = (lane & 3) * 2;
#pragma unroll
    for (int mt = 0; mt < 4; ++mt)
#pragma unroll
        for (int nt = 0; nt < 4; ++nt) {
            int row = m0 + wm * 64 + mt * 16 + gid;
            int col = n0 + wn * 32 + nt * 8 + c2;
            float* a4 = acc[mt][nt];
            if (col < 256) {
                float bb0 = b1[col], bb1 = b1[col + 1];
                *(__half2*)&g_Ah[row * 256 + col]       = __floats2half2_rn(a4[0] + bb0, a4[1] + bb1);
                *(__half2*)&g_Ah[(row + 8) * 256 + col] = __floats2half2_rn(a4[2] + bb0, a4[3] + bb1);
            } else {
                int cb = col - 256;
                *(__half2*)&g_Bh[row * 256 + cb]       = __floats2half2_rn(a4[0], a4[1]);
                *(__half2*)&g_Bh[(row + 8) * 256 + cb] = __floats2half2_rn(a4[2], a4[3]);
            }
        }
}

// ------------------------- fused GEMM2 -------------------------------------
// Block: 128 edge-rows x 128 out-cols. Gathers relu(Ah[p]+Bh[j]) full-K into
// smem once, then K-loop with double-buffered W2 via cp.async.
// Epilogue: 16-row max + b2 (max commutes with +b2).
__global__ __launch_bounds__(256) void k_gemm2(int layer, const float* __restrict__ b2,
                                               float* __restrict__ outArg, int toOut) {
    extern __shared__ __align__(16) __half dyn[];
    __half* sA = dyn;                        // 128 x 264
    __half* sW = dyn + G2_A_HALVES;          // [2][64 x 136]
    __shared__ int nbr_s[128];

    int tid = threadIdx.x, lane = tid & 31, warp = tid >> 5;
    int wm = warp & 1, wn = warp >> 1;
    int m0 = blockIdx.x * 128, n0 = blockIdx.y * 128;
    const __half* W2 = g_W2h[layer];

    // prefetch W2 stage 0 while we gather
#pragma unroll
    for (int i = tid; i < 1024; i += 256) {
        int r = i >> 4, c = (i & 15) * 8;
        cp16(&sW[r * 136 + c], &W2[(size_t)r * 256 + n0 + c]);
    }
    CP_COMMIT();

    if (tid < 128) nbr_s[tid] = g_nbr[m0 + tid];
    __syncthreads();

    // gather + relu(A_i + B_j) full K into sA  (128 rows x 256 cols)
    const __half2 z2 = __floats2half2_rn(0.f, 0.f);
#pragma unroll
    for (int i = tid; i < 4096; i += 256) {    // 128 rows x 32 chunks of 8
        int r = i >> 5, c = (i & 31) * 8;
        int p = (m0 + r) >> 4;
        int j = nbr_s[r];
        uint4 av = *(const uint4*)&g_Ah[p * 256 + c];
        uint4 bv = *(const uint4*)&g_Bh[j * 256 + c];
        __half2* ah = (__half2*)&av;
        __half2* bh = (__half2*)&bv;
        uint4 o;
        __half2* oh = (__half2*)&o;
#pragma unroll
        for (int q = 0; q < 4; ++q)
            oh[q] = __hmax2(__hadd2(ah[q], bh[q]), z2);
        *(uint4*)&sA[r * G2_A_STRIDE + c] = o;
    }

    float acc[4][4][4];
#pragma unroll
    for (int a = 0; a < 4; ++a)
#pragma unroll
        for (int b = 0; b < 4; ++b)
#pragma unroll
            for (int c = 0; c < 4; ++c) acc[a][b][c] = 0.f;

    int buf = 0;
    for (int kt = 0; kt < 4; ++kt) {
        CP_WAIT0();
        __syncthreads();
        if (kt + 1 < 4) {
            int k0 = (kt + 1) << 6;
            int nb = buf ^ 1;
#pragma unroll
            for (int i = tid; i < 1024; i += 256) {
                int r = i >> 4, c = (i & 15) * 8;
                cp16(&sW[nb * G2_W_STRIDE + r * 136 + c], &W2[(size_t)(k0 + r) * 256 + n0 + c]);
            }
            CP_COMMIT();
        }
        const __half* cW = sW + buf * G2_W_STRIDE;
        int kbase = kt * 64;
#pragma unroll
        for (int kk = 0; kk < 4; ++kk) {
            uint32_t af[4][4];
#pragma unroll
            for (int mt = 0; mt < 4; ++mt)
                ldsm4(af[mt], sptr(&sA[(wm * 64 + mt * 16 + (lane & 15)) * G2_A_STRIDE + kbase + kk * 16 + ((lane >> 4) * 8)]));
#pragma unroll
            for (int t = 0; t < 2; ++t) {
                uint32_t bf[4];
                ldsm4t(bf, sptr(&cW[(kk * 16 + (lane & 15)) * 136 + wn * 32 + t * 16 + ((lane >> 4) * 8)]));
#pragma unroll
                for (int mt = 0; mt < 4; ++mt) {
                    mma16816(acc[mt][2 * t + 0], af[mt], bf[0], bf[1]);
                    mma16816(acc[mt][2 * t + 1], af[mt], bf[2], bf[3]);
                }
            }
        }
        buf ^= 1;
    }

    float* out = toOut ? outArg : g_H;
#pragma unroll
    for (int mt = 0; mt < 4; ++mt) {
        int p = (m0 + wm * 64 + mt * 16) >> 4;
#pragma unroll
        for (int nt = 0; nt < 4; ++nt) {
            float m0v = fmaxf(acc[mt][nt][0], acc[mt][nt][2]);
            float m1v = fmaxf(acc[mt][nt][1], acc[mt][nt][3]);
#pragma unroll
            for (int off = 4; off < 32; off <<= 1) {
                m0v = fmaxf(m0v, __shfl_xor_sync(0xffffffffu, m0v, off));
                m1v = fmaxf(m1v, __shfl_xor_sync(0xffffffffu, m1v, off));
            }
            if (lane < 4) {
                int col = n0 + wn * 32 + nt * 8 + lane * 2;
                out[p * 256 + col]     = m0v + b2[col];
                out[p * 256 + col + 1] = m1v + b2[col + 1];
            }
        }
    }
}

// ------------------------- launch ------------------------------------------
extern "C" void kernel_launch(void* const* d_in, const int* in_sizes, int n_in,
                              void* d_out, int out_size) {
    const float* xyz  = (const float*)d_in[0];
    const float* feat = (const float*)d_in[1];
    const float* W1a  = (const float*)d_in[2];
    const float* b1a  = (const float*)d_in[3];
    const float* W2a  = (const float*)d_in[4];
    const float* b2a  = (const float*)d_in[5];
    const float* W1b  = (const float*)d_in[6];
    const float* b1b  = (const float*)d_in[7];
    const float* W2b  = (const float*)d_in[8];
    const float* b2b  = (const float*)d_in[9];
    float* out = (float*)d_out;

    cudaFuncSetAttribute(k_gemm1, cudaFuncAttributeMaxDynamicSharedMemorySize, SMEM1_BYTES);
    cudaFuncSetAttribute(k_gemm2, cudaFuncAttributeMaxDynamicSharedMemorySize, SMEM2_BYTES);

    k_prep_xyzw<<<32, 256>>>(xyz);
    k_knn<<<1024, 256>>>();
    k_prep_w1<<<(2 * KPAD * NOUT + 255) / 256, 256>>>(W1a, W1b);
    k_prep_w2<<<512, 256>>>(W2a, W2b);

    dim3 g1(NPTS / 128, NOUT / 128);   // 64 x 4
    dim3 g2(NEDGE / 128, 256 / 128);   // 1024 x 2

    // layer a
    k_build_x<<<(NPTS * KPAD + 255) / 256, 256>>>(feat, xyz, 0);
    k_gemm1<<<g1, 256, SMEM1_BYTES>>>(0, b1a);
    k_gemm2<<<g2, 256, SMEM2_BYTES>>>(0, b2a, nullptr, 0);

    // layer b
    k_build_x<<<(NPTS * KPAD + 255) / 256, 256>>>(nullptr, xyz, 1);
    k_gemm1<<<g1, 256, SMEM1_BYTES>>>(1, b1b);
    k_gemm2<<<g2, 256, SMEM2_BYTES>>>(1, b2b, out, 1);
}

// round 13
// speedup vs baseline: 1.2099x; 1.0413x over previous
#include <cuda_runtime.h>
#include <cuda_fp16.h>
#include <cstdint>

#define NPTS  8192
#define KNB   16
#define DIN   259
#define KPAD  320
#define NOUT  512
#define NEDGE (NPTS * KNB)

// ---- gemm1 smem (double-buffered A and B) ----
#define SA_STRIDE (128 * 72)
#define SB_STRIDE (64 * 136)
#define SMEM1_BYTES ((2 * SA_STRIDE + 2 * SB_STRIDE) * 2)

// ---- fused gemm2 smem: full-K A tile + double-buffered W2 ----
#define G2_A_STRIDE 264
#define G2_A_HALVES (128 * G2_A_STRIDE)
#define G2_W_STRIDE (64 * 136)
#define SMEM2_BYTES ((G2_A_HALVES + 2 * G2_W_STRIDE) * 2)

// ------------------------- device scratch (no allocs) ----------------------
__device__ __align__(16) float4 g_xyzw[NPTS];
__device__ int    g_nbr[NEDGE];
__device__ __align__(16) __half g_Xh[NPTS * KPAD];
__device__ __align__(16) __half g_W1h[2][KPAD * NOUT];
__device__ __align__(16) __half g_W2h[2][256 * 256];
__device__ __align__(16) __half g_Ah[NPTS * 256];   // fp16, bias folded
__device__ __align__(16) __half g_Bh[NPTS * 256];   // fp16
__device__ __align__(16) float  g_H[NPTS * 256];

// ------------------------- asm helpers -------------------------------------
__device__ __forceinline__ uint32_t sptr(const void* p) {
    return (uint32_t)__cvta_generic_to_shared(p);
}
__device__ __forceinline__ void ldsm4(uint32_t* r, uint32_t a) {
    asm volatile("ldmatrix.sync.aligned.m8n8.x4.shared.b16 {%0,%1,%2,%3},[%4];\n"
                 : "=r"(r[0]), "=r"(r[1]), "=r"(r[2]), "=r"(r[3]) : "r"(a));
}
__device__ __forceinline__ void ldsm4t(uint32_t* r, uint32_t a) {
    asm volatile("ldmatrix.sync.aligned.m8n8.x4.trans.shared.b16 {%0,%1,%2,%3},[%4];\n"
                 : "=r"(r[0]), "=r"(r[1]), "=r"(r[2]), "=r"(r[3]) : "r"(a));
}
__device__ __forceinline__ void mma16816(float* c, const uint32_t* a, uint32_t b0, uint32_t b1) {
    asm volatile(
        "mma.sync.aligned.m16n8k16.row.col.f32.f16.f16.f32 "
        "{%0,%1,%2,%3},{%4,%5,%6,%7},{%8,%9},{%0,%1,%2,%3};\n"
        : "+f"(c[0]), "+f"(c[1]), "+f"(c[2]), "+f"(c[3])
        : "r"(a[0]), "r"(a[1]), "r"(a[2]), "r"(a[3]), "r"(b0), "r"(b1));
}
__device__ __forceinline__ void cp16(void* dst, const void* src) {
    asm volatile("cp.async.cg.shared.global [%0],[%1],16;\n"
                 :: "r"(sptr(dst)), "l"(src));
}
#define CP_COMMIT() asm volatile("cp.async.commit_group;\n")
#define CP_WAIT0()  asm volatile("cp.async.wait_group 0;\n")

// ------------------------- gemm1 pipelined mainloop ------------------------
__device__ __forceinline__ void gemm_tile(const __half* __restrict__ Ag, int lda,
                                          const __half* __restrict__ Bg, int ldb,
                                          int m0, int n0, int Ksz, float acc[4][4][4]) {
    extern __shared__ __align__(16) __half dyn[];
    __half* sA = dyn;
    __half* sB = dyn + 2 * SA_STRIDE;
    int tid = threadIdx.x, lane = tid & 31, warp = tid >> 5;
    int wm = warp & 1, wn = warp >> 1;
#pragma unroll
    for (int a = 0; a < 4; ++a)
#pragma unroll
        for (int b = 0; b < 4; ++b)
#pragma unroll
            for (int c = 0; c < 4; ++c) acc[a][b][c] = 0.f;

    int nk = Ksz >> 6;
#pragma unroll
    for (int i = tid; i < 1024; i += 256) {
        int r = i >> 3, c = (i & 7) * 8;
        cp16(&sA[r * 72 + c], &Ag[(size_t)(m0 + r) * lda + c]);
    }
#pragma unroll
    for (int i = tid; i < 1024; i += 256) {
        int r = i >> 4, c = (i & 15) * 8;
        cp16(&sB[r * 136 + c], &Bg[(size_t)r * ldb + n0 + c]);
    }
    CP_COMMIT();

    int buf = 0;
    for (int kt = 0; kt < nk; ++kt) {
        CP_WAIT0();
        __syncthreads();
        if (kt + 1 < nk) {
            int k0 = (kt + 1) << 6;
            int nb = buf ^ 1;
#pragma unroll
            for (int i = tid; i < 1024; i += 256) {
                int r = i >> 3, c = (i & 7) * 8;
                cp16(&sA[nb * SA_STRIDE + r * 72 + c], &Ag[(size_t)(m0 + r) * lda + k0 + c]);
            }
#pragma unroll
            for (int i = tid; i < 1024; i += 256) {
                int r = i >> 4, c = (i & 15) * 8;
                cp16(&sB[nb * SB_STRIDE + r * 136 + c], &Bg[(size_t)(k0 + r) * ldb + n0 + c]);
            }
            CP_COMMIT();
        }
        const __half* cA = sA + buf * SA_STRIDE;
        const __half* cB = sB + buf * SB_STRIDE;
#pragma unroll
        for (int kk = 0; kk < 4; ++kk) {
            uint32_t af[4][4];
#pragma unroll
            for (int mt = 0; mt < 4; ++mt)
                ldsm4(af[mt], sptr(&cA[(wm * 64 + mt * 16 + (lane & 15)) * 72 + kk * 16 + ((lane >> 4) * 8)]));
#pragma unroll
            for (int t = 0; t < 2; ++t) {
                uint32_t bf[4];
                ldsm4t(bf, sptr(&cB[(kk * 16 + (lane & 15)) * 136 + wn * 32 + t * 16 + ((lane >> 4) * 8)]));
#pragma unroll
                for (int mt = 0; mt < 4; ++mt) {
                    mma16816(acc[mt][2 * t + 0], af[mt], bf[0], bf[1]);
                    mma16816(acc[mt][2 * t + 1], af[mt], bf[2], bf[3]);
                }
            }
        }
        buf ^= 1;
    }
}

// ------------------------- prep kernels ------------------------------------
__global__ void k_prep_xyzw(const float* __restrict__ xyz) {
    int i = blockIdx.x * blockDim.x + threadIdx.x;
    if (i < NPTS) {
        float x = xyz[3 * i], y = xyz[3 * i + 1], z = xyz[3 * i + 2];
        g_xyzw[i] = make_float4(x, y, z, x * x + y * y + z * z);
    }
}

__global__ void k_prep_w1(const float* __restrict__ W1a, const float* __restrict__ W1b) {
    int idx = blockIdx.x * blockDim.x + threadIdx.x;
    if (idx >= 2 * KPAD * NOUT) return;
    int layer = idx / (KPAD * NOUT);
    int rem = idx % (KPAD * NOUT);
    int k = rem / NOUT, n = rem % NOUT;
    const float* W1 = layer ? W1b : W1a;
    float v = 0.f;
    if (k < DIN) {
        if (n < 256) v = W1[k * 256 + n] - W1[(DIN + k) * 256 + n];
        else         v = W1[(DIN + k) * 256 + (n - 256)];
    }
    g_W1h[layer][rem] = __float2half_rn(v);
}

__global__ void k_prep_w2(const float* __restrict__ W2a, const float* __restrict__ W2b) {
    int idx = blockIdx.x * blockDim.x + threadIdx.x;
    if (idx >= 2 * 256 * 256) return;
    int layer = idx >> 16, rem = idx & 65535;
    g_W2h[layer][rem] = __float2half_rn((layer ? W2b : W2a)[rem]);
}

__global__ void k_build_x(const float* __restrict__ feat, const float* __restrict__ xyz, int useH) {
    int idx = blockIdx.x * blockDim.x + threadIdx.x;
    if (idx >= NPTS * KPAD) return;
    int r = idx / KPAD, c = idx % KPAD;
    const float* s = useH ? g_H : feat;
    float v = 0.f;
    if (c < 256)      v = s[r * 256 + c];
    else if (c < DIN) v = xyz[r * 3 + (c - 256)];
    g_Xh[idx] = __float2half_rn(v);
}

// ------------------------- KNN (warp-shared threshold gate) ----------------
__global__ __launch_bounds__(256) void k_knn() {
    __shared__ float4 tile[2048];
    int lane = threadIdx.x & 31, warp = threadIdx.x >> 5;
    int row = blockIdx.x * 8 + warp;
    float4 me = g_xyzw[row];

    float bd[16]; int bi[16];
#pragma unroll
    for (int p = 0; p < 16; ++p) { bd[p] = 3.4e38f; bi[p] = 0x7fffffff; }

    float tau = 3.4e38f;   // warp-shared gate: min over lanes of bd[15] (lazy)

    for (int t = 0; t < 4; ++t) {
        __syncthreads();
        for (int i = threadIdx.x; i < 2048; i += 256) tile[i] = g_xyzw[t * 2048 + i];
        __syncthreads();
        int jg0 = t * 2048;
        int it = 0;
        for (int jj = lane; jj < 2048; jj += 32, ++it) {
            float4 o = tile[jj];
            float key = fmaf(-2.f * me.x, o.x, o.w);
            key = fmaf(-2.f * me.y, o.y, key);
            key = fmaf(-2.f * me.z, o.z, key);
            int jg = jg0 + jj;
            // gate on warp-shared tau: tau <= own bd[15] always, so this
            // subsumes the per-lane check; tau >= running global 16th.
            if (jg != row && key < tau) {
                bd[15] = key; bi[15] = jg;
#pragma unroll
                for (int p = 15; p > 0; --p) {
                    if (bd[p] < bd[p - 1]) {
                        float td = bd[p]; bd[p] = bd[p - 1]; bd[p - 1] = td;
                        int ti = bi[p]; bi[p] = bi[p - 1]; bi[p - 1] = ti;
                    }
                }
            }
            if ((it & 7) == 7) {   // refresh tau (uniform control flow)
                float w = bd[15];
#pragma unroll
                for (int off = 16; off > 0; off >>= 1)
                    w = fminf(w, __shfl_xor_sync(0xffffffffu, w, off));
                tau = w;
            }
        }
    }
    // merge 32 sorted per-lane lists -> global top-16 (min key, index tiebreak)
    float v = bd[0]; int vi = bi[0];
    int keep = 0;
    for (int r = 0; r < 16; ++r) {
        float mv = v; int mi = vi;
#pragma unroll
        for (int off = 16; off > 0; off >>= 1) {
            float ov = __shfl_xor_sync(0xffffffffu, mv, off);
            int   oi = __shfl_xor_sync(0xffffffffu, mi, off);
            if (ov < mv || (ov == mv && oi < mi)) { mv = ov; mi = oi; }
        }
        if (lane == r) keep = mi;
        if (v == mv && vi == mi) {
#pragma unroll
            for (int p = 0; p < 15; ++p) { bd[p] = bd[p + 1]; bi[p] = bi[p + 1]; }
            bd[15] = 3.4e38f; bi[15] = 0x7fffffff;
            v = bd[0]; vi = bi[0];
        }
    }
    if (lane < 16) g_nbr[row * 16 + lane] = keep;
}

// ------------------------- GEMM1: X @ W1cat -> fp16 A (bias) / B -----------
__global__ __launch_bounds__(256) void k_gemm1(int layer, const float* __restrict__ b1) {
    float acc[4][4][4];
    int m0 = blockIdx.x * 128, n0 = blockIdx.y * 128;
    gemm_tile(g_Xh, KPAD, g_W1h[layer], NOUT, m0, n0, KPAD, acc);

    int lane = threadIdx.x & 31, warp = threadIdx.x >> 5;
    int wm = warp & 1, wn = warp >> 1;
    int gid = lane >> 2, c2 = (lane & 3) * 2;
#pragma unroll
    for (int mt = 0; mt < 4; ++mt)
#pragma unroll
        for (int nt = 0; nt < 4; ++nt) {
            int row = m0 + wm * 64 + mt * 16 + gid;
            int col = n0 + wn * 32 + nt * 8 + c2;
            float* a4 = acc[mt][nt];
            if (col < 256) {
                float bb0 = b1[col], bb1 = b1[col + 1];
                *(__half2*)&g_Ah[row * 256 + col]       = __floats2half2_rn(a4[0] + bb0, a4[1] + bb1);
                *(__half2*)&g_Ah[(row + 8) * 256 + col] = __floats2half2_rn(a4[2] + bb0, a4[3] + bb1);
            } else {
                int cb = col - 256;
                *(__half2*)&g_Bh[row * 256 + cb]       = __floats2half2_rn(a4[0], a4[1]);
                *(__half2*)&g_Bh[(row + 8) * 256 + cb] = __floats2half2_rn(a4[2], a4[3]);
            }
        }
}

// ------------------------- fused GEMM2 -------------------------------------
__global__ __launch_bounds__(256) void k_gemm2(int layer, const float* __restrict__ b2,
                                               float* __restrict__ outArg, int toOut) {
    extern __shared__ __align__(16) __half dyn[];
    __half* sA = dyn;                        // 128 x 264
    __half* sW = dyn + G2_A_HALVES;          // [2][64 x 136]
    __shared__ int nbr_s[128];

    int tid = threadIdx.x, lane = tid & 31, warp = tid >> 5;
    int wm = warp & 1, wn = warp >> 1;
    int m0 = blockIdx.x * 128, n0 = blockIdx.y * 128;
    const __half* W2 = g_W2h[layer];

#pragma unroll
    for (int i = tid; i < 1024; i += 256) {
        int r = i >> 4, c = (i & 15) * 8;
        cp16(&sW[r * 136 + c], &W2[(size_t)r * 256 + n0 + c]);
    }
    CP_COMMIT();

    if (tid < 128) nbr_s[tid] = g_nbr[m0 + tid];
    __syncthreads();

    const __half2 z2 = __floats2half2_rn(0.f, 0.f);
#pragma unroll
    for (int i = tid; i < 4096; i += 256) {
        int r = i >> 5, c = (i & 31) * 8;
        int p = (m0 + r) >> 4;
        int j = nbr_s[r];
        uint4 av = *(const uint4*)&g_Ah[p * 256 + c];
        uint4 bv = *(const uint4*)&g_Bh[j * 256 + c];
        __half2* ah = (__half2*)&av;
        __half2* bh = (__half2*)&bv;
        uint4 o;
        __half2* oh = (__half2*)&o;
#pragma unroll
        for (int q = 0; q < 4; ++q)
            oh[q] = __hmax2(__hadd2(ah[q], bh[q]), z2);
        *(uint4*)&sA[r * G2_A_STRIDE + c] = o;
    }

    float acc[4][4][4];
#pragma unroll
    for (int a = 0; a < 4; ++a)
#pragma unroll
        for (int b = 0; b < 4; ++b)
#pragma unroll
            for (int c = 0; c < 4; ++c) acc[a][b][c] = 0.f;

    int buf = 0;
    for (int kt = 0; kt < 4; ++kt) {
        CP_WAIT0();
        __syncthreads();
        if (kt + 1 < 4) {
            int k0 = (kt + 1) << 6;
            int nb = buf ^ 1;
#pragma unroll
            for (int i = tid; i < 1024; i += 256) {
                int r = i >> 4, c = (i & 15) * 8;
                cp16(&sW[nb * G2_W_STRIDE + r * 136 + c], &W2[(size_t)(k0 + r) * 256 + n0 + c]);
            }
            CP_COMMIT();
        }
        const __half* cW = sW + buf * G2_W_STRIDE;
        int kbase = kt * 64;
#pragma unroll
        for (int kk = 0; kk < 4; ++kk) {
            uint32_t af[4][4];
#pragma unroll
            for (int mt = 0; mt < 4; ++mt)
                ldsm4(af[mt], sptr(&sA[(wm * 64 + mt * 16 + (lane & 15)) * G2_A_STRIDE + kbase + kk * 16 + ((lane >> 4) * 8)]));
#pragma unroll
            for (int t = 0; t < 2; ++t) {
                uint32_t bf[4];
                ldsm4t(bf, sptr(&cW[(kk * 16 + (lane & 15)) * 136 + wn * 32 + t * 16 + ((lane >> 4) * 8)]));
#pragma unroll
                for (int mt = 0; mt < 4; ++mt) {
                    mma16816(acc[mt][2 * t + 0], af[mt], bf[0], bf[1]);
                    mma16816(acc[mt][2 * t + 1], af[mt], bf[2], bf[3]);
                }
            }
        }
        buf ^= 1;
    }

    float* out = toOut ? outArg : g_H;
#pragma unroll
    for (int mt = 0; mt < 4; ++mt) {
        int p = (m0 + wm * 64 + mt * 16) >> 4;
#pragma unroll
        for (int nt = 0; nt < 4; ++nt) {
            float m0v = fmaxf(acc[mt][nt][0], acc[mt][nt][2]);
            float m1v = fmaxf(acc[mt][nt][1], acc[mt][nt][3]);
#pragma unroll
            for (int off = 4; off < 32; off <<= 1) {
                m0v = fmaxf(m0v, __shfl_xor_sync(0xffffffffu, m0v, off));
                m1v = fmaxf(m1v, __shfl_xor_sync(0xffffffffu, m1v, off));
            }
            if (lane < 4) {
                int col = n0 + wn * 32 + nt * 8 + lane * 2;
                out[p * 256 + col]     = m0v + b2[col];
                out[p * 256 + col + 1] = m1v + b2[col + 1];
            }
        }
    }
}

// ------------------------- launch ------------------------------------------
extern "C" void kernel_launch(void* const* d_in, const int* in_sizes, int n_in,
                              void* d_out, int out_size) {
    const float* xyz  = (const float*)d_in[0];
    const float* feat = (const float*)d_in[1];
    const float* W1a  = (const float*)d_in[2];
    const float* b1a  = (const float*)d_in[3];
    const float* W2a  = (const float*)d_in[4];
    const float* b2a  = (const float*)d_in[5];
    const float* W1b  = (const float*)d_in[6];
    const float* b1b  = (const float*)d_in[7];
    const float* W2b  = (const float*)d_in[8];
    const float* b2b  = (const float*)d_in[9];
    float* out = (float*)d_out;

    cudaFuncSetAttribute(k_gemm1, cudaFuncAttributeMaxDynamicSharedMemorySize, SMEM1_BYTES);
    cudaFuncSetAttribute(k_gemm2, cudaFuncAttributeMaxDynamicSharedMemorySize, SMEM2_BYTES);

    // reordered so the ncu -s 5 -c 1 window lands on the heavy path (knn)
    k_prep_w1<<<(2 * KPAD * NOUT + 255) / 256, 256>>>(W1a, W1b);
    k_prep_w2<<<512, 256>>>(W2a, W2b);
    k_prep_xyzw<<<32, 256>>>(xyz);
    k_knn<<<1024, 256>>>();

    dim3 g1(NPTS / 128, NOUT / 128);
    dim3 g2(NEDGE / 128, 256 / 128);

    // layer a
    k_build_x<<<(NPTS * KPAD + 255) / 256, 256>>>(feat, xyz, 0);
    k_gemm1<<<g1, 256, SMEM1_BYTES>>>(0, b1a);
    k_gemm2<<<g2, 256, SMEM2_BYTES>>>(0, b2a, nullptr, 0);

    // layer b
    k_build_x<<<(NPTS * KPAD + 255) / 256, 256>>>(nullptr, xyz, 1);
    k_gemm1<<<g1, 256, SMEM1_BYTES>>>(1, b1b);
    k_gemm2<<<g2, 256, SMEM2_BYTES>>>(1, b2b, out, 1);
}

// round 15
// speedup vs baseline: 1.5827x; 1.3081x over previous
#include <cuda_runtime.h>
#include <cuda_fp16.h>
#include <cstdint>

#define NPTS  8192
#define KNB   16
#define DIN   259
#define KPAD  320
#define NOUT  512
#define NEDGE (NPTS * KNB)

// ---- gemm1 smem (double-buffered A and B) ----
#define SA_STRIDE (128 * 72)
#define SB_STRIDE (64 * 136)
#define SMEM1_BYTES ((2 * SA_STRIDE + 2 * SB_STRIDE) * 2)

// ---- fused gemm2 smem: full-K A tile + double-buffered W2 ----
#define G2_A_STRIDE 264
#define G2_A_HALVES (128 * G2_A_STRIDE)
#define G2_W_STRIDE (64 * 136)
#define SMEM2_BYTES ((G2_A_HALVES + 2 * G2_W_STRIDE) * 2)

// ---- knn pool ----
#define POOL_CAP 112     // 16 kept + up to 96 buffered (trigger at >80, +<=32)

// ------------------------- device scratch (no allocs) ----------------------
__device__ __align__(16) float4 g_xyzw[NPTS];
__device__ int    g_nbr[NEDGE];
__device__ __align__(16) __half g_Xh[NPTS * KPAD];
__device__ __align__(16) __half g_W1h[2][KPAD * NOUT];
__device__ __align__(16) __half g_W2h[2][256 * 256];
__device__ __align__(16) __half g_Ah[NPTS * 256];   // fp16, bias folded
__device__ __align__(16) __half g_Bh[NPTS * 256];   // fp16
__device__ __align__(16) float  g_H[NPTS * 256];

// ------------------------- asm helpers -------------------------------------
__device__ __forceinline__ uint32_t sptr(const void* p) {
    return (uint32_t)__cvta_generic_to_shared(p);
}
__device__ __forceinline__ void ldsm4(uint32_t* r, uint32_t a) {
    asm volatile("ldmatrix.sync.aligned.m8n8.x4.shared.b16 {%0,%1,%2,%3},[%4];\n"
                 : "=r"(r[0]), "=r"(r[1]), "=r"(r[2]), "=r"(r[3]) : "r"(a));
}
__device__ __forceinline__ void ldsm4t(uint32_t* r, uint32_t a) {
    asm volatile("ldmatrix.sync.aligned.m8n8.x4.trans.shared.b16 {%0,%1,%2,%3},[%4];\n"
                 : "=r"(r[0]), "=r"(r[1]), "=r"(r[2]), "=r"(r[3]) : "r"(a));
}
__device__ __forceinline__ void mma16816(float* c, const uint32_t* a, uint32_t b0, uint32_t b1) {
    asm volatile(
        "mma.sync.aligned.m16n8k16.row.col.f32.f16.f16.f32 "
        "{%0,%1,%2,%3},{%4,%5,%6,%7},{%8,%9},{%0,%1,%2,%3};\n"
        : "+f"(c[0]), "+f"(c[1]), "+f"(c[2]), "+f"(c[3])
        : "r"(a[0]), "r"(a[1]), "r"(a[2]), "r"(a[3]), "r"(b0), "r"(b1));
}
__device__ __forceinline__ void cp16(void* dst, const void* src) {
    asm volatile("cp.async.cg.shared.global [%0],[%1],16;\n"
                 :: "r"(sptr(dst)), "l"(src));
}
#define CP_COMMIT() asm volatile("cp.async.commit_group;\n")
#define CP_WAIT0()  asm volatile("cp.async.wait_group 0;\n")

// ------------------------- gemm1 pipelined mainloop ------------------------
__device__ __forceinline__ void gemm_tile(const __half* __restrict__ Ag, int lda,
                                          const __half* __restrict__ Bg, int ldb,
                                          int m0, int n0, int Ksz, float acc[4][4][4]) {
    extern __shared__ __align__(16) __half dyn[];
    __half* sA = dyn;
    __half* sB = dyn + 2 * SA_STRIDE;
    int tid = threadIdx.x, lane = tid & 31, warp = tid >> 5;
    int wm = warp & 1, wn = warp >> 1;
#pragma unroll
    for (int a = 0; a < 4; ++a)
#pragma unroll
        for (int b = 0; b < 4; ++b)
#pragma unroll
            for (int c = 0; c < 4; ++c) acc[a][b][c] = 0.f;

    int nk = Ksz >> 6;
#pragma unroll
    for (int i = tid; i < 1024; i += 256) {
        int r = i >> 3, c = (i & 7) * 8;
        cp16(&sA[r * 72 + c], &Ag[(size_t)(m0 + r) * lda + c]);
    }
#pragma unroll
    for (int i = tid; i < 1024; i += 256) {
        int r = i >> 4, c = (i & 15) * 8;
        cp16(&sB[r * 136 + c], &Bg[(size_t)r * ldb + n0 + c]);
    }
    CP_COMMIT();

    int buf = 0;
    for (int kt = 0; kt < nk; ++kt) {
        CP_WAIT0();
        __syncthreads();
        if (kt + 1 < nk) {
            int k0 = (kt + 1) << 6;
            int nb = buf ^ 1;
#pragma unroll
            for (int i = tid; i < 1024; i += 256) {
                int r = i >> 3, c = (i & 7) * 8;
                cp16(&sA[nb * SA_STRIDE + r * 72 + c], &Ag[(size_t)(m0 + r) * lda + k0 + c]);
            }
#pragma unroll
            for (int i = tid; i < 1024; i += 256) {
                int r = i >> 4, c = (i & 15) * 8;
                cp16(&sB[nb * SB_STRIDE + r * 136 + c], &Bg[(size_t)(k0 + r) * ldb + n0 + c]);
            }
            CP_COMMIT();
        }
        const __half* cA = sA + buf * SA_STRIDE;
        const __half* cB = sB + buf * SB_STRIDE;
#pragma unroll
        for (int kk = 0; kk < 4; ++kk) {
            uint32_t af[4][4];
#pragma unroll
            for (int mt = 0; mt < 4; ++mt)
                ldsm4(af[mt], sptr(&cA[(wm * 64 + mt * 16 + (lane & 15)) * 72 + kk * 16 + ((lane >> 4) * 8)]));
#pragma unroll
            for (int t = 0; t < 2; ++t) {
                uint32_t bf[4];
                ldsm4t(bf, sptr(&cB[(kk * 16 + (lane & 15)) * 136 + wn * 32 + t * 16 + ((lane >> 4) * 8)]));
#pragma unroll
                for (int mt = 0; mt < 4; ++mt) {
                    mma16816(acc[mt][2 * t + 0], af[mt], bf[0], bf[1]);
                    mma16816(acc[mt][2 * t + 1], af[mt], bf[2], bf[3]);
                }
            }
        }
        buf ^= 1;
    }
}

// ------------------------- prep kernels ------------------------------------
__global__ void k_prep_xyzw(const float* __restrict__ xyz) {
    int i = blockIdx.x * blockDim.x + threadIdx.x;
    if (i < NPTS) {
        float x = xyz[3 * i], y = xyz[3 * i + 1], z = xyz[3 * i + 2];
        g_xyzw[i] = make_float4(x, y, z, x * x + y * y + z * z);
    }
}

__global__ void k_prep_w1(const float* __restrict__ W1a, const float* __restrict__ W1b) {
    int idx = blockIdx.x * blockDim.x + threadIdx.x;
    if (idx >= 2 * KPAD * NOUT) return;
    int layer = idx / (KPAD * NOUT);
    int rem = idx % (KPAD * NOUT);
    int k = rem / NOUT, n = rem % NOUT;
    const float* W1 = layer ? W1b : W1a;
    float v = 0.f;
    if (k < DIN) {
        if (n < 256) v = W1[k * 256 + n] - W1[(DIN + k) * 256 + n];
        else         v = W1[(DIN + k) * 256 + (n - 256)];
    }
    g_W1h[layer][rem] = __float2half_rn(v);
}

__global__ void k_prep_w2(const float* __restrict__ W2a, const float* __restrict__ W2b) {
    int idx = blockIdx.x * blockDim.x + threadIdx.x;
    if (idx >= 2 * 256 * 256) return;
    int layer = idx >> 16, rem = idx & 65535;
    g_W2h[layer][rem] = __float2half_rn((layer ? W2b : W2a)[rem]);
}

__global__ void k_build_x(const float* __restrict__ feat, const float* __restrict__ xyz, int useH) {
    int idx = blockIdx.x * blockDim.x + threadIdx.x;
    if (idx >= NPTS * KPAD) return;
    int r = idx / KPAD, c = idx % KPAD;
    const float* s = useH ? g_H : feat;
    float v = 0.f;
    if (c < 256)      v = s[r * 256 + c];
    else if (c < DIN) v = xyz[r * 3 + (c - 256)];
    g_Xh[idx] = __float2half_rn(v);
}

// ------------------------- KNN (ballot-append + warp refine) ---------------
// Warp-shared pool (smem): slots [0,16) = current top-16 (sorted after refine),
// [16,cnt) = appended candidates. refine() extracts the 16 smallest
// (lexicographic (key,idx) — jax tie semantics), sets cnt=16, tau=16th.
__device__ __forceinline__ void knn_refine(float* bk, int* bi, int& cnt, float& tau, int lane) {
    float k[4]; int id[4];
#pragma unroll
    for (int q = 0; q < 4; ++q) {
        int s = lane + 32 * q;
        if (s < cnt) { k[q] = bk[s]; id[q] = bi[s]; }
        else         { k[q] = 3.4e38f; id[q] = 0x7fffffff; }
    }
    __syncwarp();
#pragma unroll
    for (int r = 0; r < 16; ++r) {
        float lm = k[0]; int li = id[0]; int ls = 0;
#pragma unroll
        for (int q = 1; q < 4; ++q)
            if (k[q] < lm || (k[q] == lm && id[q] < li)) { lm = k[q]; li = id[q]; ls = q; }
        float mv = lm; int mi = li;
#pragma unroll
        for (int off = 16; off > 0; off >>= 1) {
            float ov = __shfl_xor_sync(0xffffffffu, mv, off);
            int   oi = __shfl_xor_sync(0xffffffffu, mi, off);
            if (ov < mv || (ov == mv && oi < mi)) { mv = ov; mi = oi; }
        }
        if (lm == mv && li == mi) { k[ls] = 3.4e38f; id[ls] = 0x7fffffff; }
        if (lane == 0) { bk[r] = mv; bi[r] = mi; }
    }
    __syncwarp();
    cnt = 16;
    tau = bk[15];
    __syncwarp();
}

__global__ __launch_bounds__(256) void k_knn() {
    __shared__ float4 tile[2048];
    __shared__ float s_bk[8][POOL_CAP];
    __shared__ int   s_bi[8][POOL_CAP];
    int lane = threadIdx.x & 31, warp = threadIdx.x >> 5;
    int row = blockIdx.x * 8 + warp;
    float4 me = g_xyzw[row];
    float* bk = s_bk[warp];
    int*   bi = s_bi[warp];
    int cnt = 0;            // warp-uniform
    float tau = 3.4e38f;    // warp-uniform; always >= true running 16th

    for (int t = 0; t < 4; ++t) {
        __syncthreads();
        for (int i = threadIdx.x; i < 2048; i += 256) tile[i] = g_xyzw[t * 2048 + i];
        __syncthreads();
        int jg0 = t * 2048;
        for (int jj = lane; jj < 2048; jj += 32) {
            float4 o = tile[jj];
            float key = fmaf(-2.f * me.x, o.x, o.w);
            key = fmaf(-2.f * me.y, o.y, key);
            key = fmaf(-2.f * me.z, o.z, key);
            int jg = jg0 + jj;
            bool pass = (key < tau) && (jg != row);
            unsigned m = __ballot_sync(0xffffffffu, pass);
            if (m) {
                int off = __popc(m & ((1u << lane) - 1));
                if (pass) { bk[cnt + off] = key; bi[cnt + off] = jg; }
                __syncwarp();
                cnt += __popc(m);
                if (cnt > 80) knn_refine(bk, bi, cnt, tau, lane);
            }
        }
    }
    knn_refine(bk, bi, cnt, tau, lane);   // final sort of top-16
    if (lane < 16) g_nbr[row * 16 + lane] = bi[lane];
}

// ------------------------- GEMM1: X @ W1cat -> fp16 A (bias) / B -----------
__global__ __launch_bounds__(256) void k_gemm1(int layer, const float* __restrict__ b1) {
    float acc[4][4][4];
    int m0 = blockIdx.x * 128, n0 = blockIdx.y * 128;
    gemm_tile(g_Xh, KPAD, g_W1h[layer], NOUT, m0, n0, KPAD, acc);

    int lane = threadIdx.x & 31, warp = threadIdx.x >> 5;
    int wm = warp & 1, wn = warp >> 1;
    int gid = lane >> 2, c2 = (lane & 3) * 2;
#pragma unroll
    for (int mt = 0; mt < 4; ++mt)
#pragma unroll
        for (int nt = 0; nt < 4; ++nt) {
            int row = m0 + wm * 64 + mt * 16 + gid;
            int col = n0 + wn * 32 + nt * 8 + c2;
            float* a4 = acc[mt][nt];
            if (col < 256) {
                float bb0 = b1[col], bb1 = b1[col + 1];
                *(__half2*)&g_Ah[row * 256 + col]       = __floats2half2_rn(a4[0] + bb0, a4[1] + bb1);
                *(__half2*)&g_Ah[(row + 8) * 256 + col] = __floats2half2_rn(a4[2] + bb0, a4[3] + bb1);
            } else {
                int cb = col - 256;
                *(__half2*)&g_Bh[row * 256 + cb]       = __floats2half2_rn(a4[0], a4[1]);
                *(__half2*)&g_Bh[(row + 8) * 256 + cb] = __floats2half2_rn(a4[2], a4[3]);
            }
        }
}

// ------------------------- fused GEMM2 -------------------------------------
__global__ __launch_bounds__(256) void k_gemm2(int layer, const float* __restrict__ b2,
                                               float* __restrict__ outArg, int toOut) {
    extern __shared__ __align__(16) __half dyn[];
    __half* sA = dyn;                        // 128 x 264
    __half* sW = dyn + G2_A_HALVES;          // [2][64 x 136]
    __shared__ int nbr_s[128];

    int tid = threadIdx.x, lane = tid & 31, warp = tid >> 5;
    int wm = warp & 1, wn = warp >> 1;
    int m0 = blockIdx.x * 128, n0 = blockIdx.y * 128;
    const __half* W2 = g_W2h[layer];

#pragma unroll
    for (int i = tid; i < 1024; i += 256) {
        int r = i >> 4, c = (i & 15) * 8;
        cp16(&sW[r * 136 + c], &W2[(size_t)r * 256 + n0 + c]);
    }
    CP_COMMIT();

    if (tid < 128) nbr_s[tid] = g_nbr[m0 + tid];
    __syncthreads();

    const __half2 z2 = __floats2half2_rn(0.f, 0.f);
#pragma unroll
    for (int i = tid; i < 4096; i += 256) {
        int r = i >> 5, c = (i & 31) * 8;
        int p = (m0 + r) >> 4;
        int j = nbr_s[r];
        uint4 av = *(const uint4*)&g_Ah[p * 256 + c];
        uint4 bv = *(const uint4*)&g_Bh[j * 256 + c];
        __half2* ah = (__half2*)&av;
        __half2* bh = (__half2*)&bv;
        uint4 o;
        __half2* oh = (__half2*)&o;
#pragma unroll
        for (int q = 0; q < 4; ++q)
            oh[q] = __hmax2(__hadd2(ah[q], bh[q]), z2);
        *(uint4*)&sA[r * G2_A_STRIDE + c] = o;
    }

    float acc[4][4][4];
#pragma unroll
    for (int a = 0; a < 4; ++a)
#pragma unroll
        for (int b = 0; b < 4; ++b)
#pragma unroll
            for (int c = 0; c < 4; ++c) acc[a][b][c] = 0.f;

    int buf = 0;
    for (int kt = 0; kt < 4; ++kt) {
        CP_WAIT0();
        __syncthreads();
        if (kt + 1 < 4) {
            int k0 = (kt + 1) << 6;
            int nb = buf ^ 1;
#pragma unroll
            for (int i = tid; i < 1024; i += 256) {
                int r = i >> 4, c = (i & 15) * 8;
                cp16(&sW[nb * G2_W_STRIDE + r * 136 + c], &W2[(size_t)(k0 + r) * 256 + n0 + c]);
            }
            CP_COMMIT();
        }
        const __half* cW = sW + buf * G2_W_STRIDE;
        int kbase = kt * 64;
#pragma unroll
        for (int kk = 0; kk < 4; ++kk) {
            uint32_t af[4][4];
#pragma unroll
            for (int mt = 0; mt < 4; ++mt)
                ldsm4(af[mt], sptr(&sA[(wm * 64 + mt * 16 + (lane & 15)) * G2_A_STRIDE + kbase + kk * 16 + ((lane >> 4) * 8)]));
#pragma unroll
            for (int t = 0; t < 2; ++t) {
                uint32_t bf[4];
                ldsm4t(bf, sptr(&cW[(kk * 16 + (lane & 15)) * 136 + wn * 32 + t * 16 + ((lane >> 4) * 8)]));
#pragma unroll
                for (int mt = 0; mt < 4; ++mt) {
                    mma16816(acc[mt][2 * t + 0], af[mt], bf[0], bf[1]);
                    mma16816(acc[mt][2 * t + 1], af[mt], bf[2], bf[3]);
                }
            }
        }
        buf ^= 1;
    }

    float* out = toOut ? outArg : g_H;
#pragma unroll
    for (int mt = 0; mt < 4; ++mt) {
        int p = (m0 + wm * 64 + mt * 16) >> 4;
#pragma unroll
        for (int nt = 0; nt < 4; ++nt) {
            float m0v = fmaxf(acc[mt][nt][0], acc[mt][nt][2]);
            float m1v = fmaxf(acc[mt][nt][1], acc[mt][nt][3]);
#pragma unroll
            for (int off = 4; off < 32; off <<= 1) {
                m0v = fmaxf(m0v, __shfl_xor_sync(0xffffffffu, m0v, off));
                m1v = fmaxf(m1v, __shfl_xor_sync(0xffffffffu, m1v, off));
            }
            if (lane < 4) {
                int col = n0 + wn * 32 + nt * 8 + lane * 2;
                out[p * 256 + col]     = m0v + b2[col];
                out[p * 256 + col + 1] = m1v + b2[col + 1];
            }
        }
    }
}

// ------------------------- launch ------------------------------------------
extern "C" void kernel_launch(void* const* d_in, const int* in_sizes, int n_in,
                              void* d_out, int out_size) {
    const float* xyz  = (const float*)d_in[0];
    const float* feat = (const float*)d_in[1];
    const float* W1a  = (const float*)d_in[2];
    const float* b1a  = (const float*)d_in[3];
    const float* W2a  = (const float*)d_in[4];
    const float* b2a  = (const float*)d_in[5];
    const float* W1b  = (const float*)d_in[6];
    const float* b1b  = (const float*)d_in[7];
    const float* W2b  = (const float*)d_in[8];
    const float* b2b  = (const float*)d_in[9];
    float* out = (float*)d_out;

    cudaFuncSetAttribute(k_gemm1, cudaFuncAttributeMaxDynamicSharedMemorySize, SMEM1_BYTES);
    cudaFuncSetAttribute(k_gemm2, cudaFuncAttributeMaxDynamicSharedMemorySize, SMEM2_BYTES);

    // ncu -s 5 -c 1 window: keep knn as the 4th launch for another profile,
    // heavy gemm2 comes right after for future windows.
    k_prep_w1<<<(2 * KPAD * NOUT + 255) / 256, 256>>>(W1a, W1b);
    k_prep_w2<<<512, 256>>>(W2a, W2b);
    k_prep_xyzw<<<32, 256>>>(xyz);
    k_knn<<<1024, 256>>>();

    dim3 g1(NPTS / 128, NOUT / 128);
    dim3 g2(NEDGE / 128, 256 / 128);

    // layer a
    k_build_x<<<(NPTS * KPAD + 255) / 256, 256>>>(feat, xyz, 0);
    k_gemm1<<<g1, 256, SMEM1_BYTES>>>(0, b1a);
    k_gemm2<<<g2, 256, SMEM2_BYTES>>>(0, b2a, nullptr, 0);

    // layer b
    k_build_x<<<(NPTS * KPAD + 255) / 256, 256>>>(nullptr, xyz, 1);
    k_gemm1<<<g1, 256, SMEM1_BYTES>>>(1, b1b);
    k_gemm2<<<g2, 256, SMEM2_BYTES>>>(1, b2b, out, 1);
}